// round 12
// baseline (speedup 1.0000x reference)
#include <cuda_runtime.h>
#include <cuda_bf16.h>
#include <cuda_fp16.h>
#include <stdint.h>

// ---------------------------------------------------------------------------
// Problem constants
// ---------------------------------------------------------------------------
#define N_ROBOT 100000
#define N_BALL  100000
#define E_MAX   600000
#define GB_ROBOT ((N_ROBOT + 63) / 64)   // 1563
#define GB_BALL  ((N_BALL + 63) / 64)    // 1563

// ---------------------------------------------------------------------------
// Scratch (device globals; allocation is forbidden)
// ---------------------------------------------------------------------------
#define O_TRR     0ull
#define O_TBR     (O_TRR + 6400000ull)
#define O_FR      (O_TBR + 6400000ull)
#define O_BSUM0   (O_FR  + 6400000ull)
#define O_BSUM1   (O_BSUM0 + 128ull)
#define O_WB0_RR  (O_BSUM1 + 64ull)
#define O_WB0_BR  (O_WB0_RR + 17408ull)
#define O_WBSUM0  (O_WB0_BR + 17408ull)
#define O_WB0_RB  (O_WBSUM0 + 17408ull)
#define O_WBR0_RB (O_WB0_RB + 17408ull)
#define O_WB1_RR  (O_WBR0_RB + 17408ull)
#define O_WBSUM1  (O_WB1_RR + 8704ull)
#define O_WB1_BR  (O_WBSUM1 + 8704ull)
#define O_XH_R    (O_WB1_BR + 8704ull)     // fp16 x_robot: 12.8M halfs = 6.4M floats
#define O_XH_B    (O_XH_R + 6400000ull)
#define SCRATCH_FLOATS (O_XH_B + 6400000ull)

__device__ float g_scratch[SCRATCH_FLOATS];
__device__ int   g_cnt[3 * N_ROBOT];
__device__ int   g_off[3 * N_ROBOT];
__device__ int   g_cursor[3 * N_ROBOT];
__device__ int   g_csr[3 * E_MAX + 64];
__device__ int   g_bsum[1024];

#define NSCAN   (3 * N_ROBOT)
#define SCAN_BS 512
#define SCAN_NB ((NSCAN + SCAN_BS - 1) / SCAN_BS)

// ---------------------------------------------------------------------------
// Helpers (baseline PTX only)
// ---------------------------------------------------------------------------
__device__ __forceinline__ uint32_t smem_u32(const void* p) {
    uint32_t a;
    asm("{ .reg .u64 t; cvta.to.shared.u64 t, %1; cvt.u32.u64 %0, t; }"
        : "=r"(a) : "l"(p));
    return a;
}

#define LDSM_X4(r0, r1, r2, r3, addr) \
    asm volatile("ldmatrix.sync.aligned.m8n8.x4.shared.b16 {%0,%1,%2,%3}, [%4];" \
                 : "=r"(r0), "=r"(r1), "=r"(r2), "=r"(r3) : "r"(addr))

__device__ __forceinline__ void mma_bf16(float* c, const uint32_t* a,
                                         uint32_t b0, uint32_t b1) {
    asm volatile(
        "mma.sync.aligned.m16n8k16.row.col.f32.bf16.bf16.f32 "
        "{%0,%1,%2,%3}, {%4,%5,%6,%7}, {%8,%9}, {%0,%1,%2,%3};"
        : "+f"(c[0]), "+f"(c[1]), "+f"(c[2]), "+f"(c[3])
        : "r"(a[0]), "r"(a[1]), "r"(a[2]), "r"(a[3]), "r"(b0), "r"(b1));
}

__device__ __forceinline__ void split_pack(float x0, float x1,
                                           uint32_t& hp, uint32_t& lp) {
    __nv_bfloat16 h0 = __float2bfloat16(x0);
    __nv_bfloat16 h1 = __float2bfloat16(x1);
    __nv_bfloat16 l0 = __float2bfloat16(x0 - __bfloat162float(h0));
    __nv_bfloat16 l1 = __float2bfloat16(x1 - __bfloat162float(h1));
    hp = ((uint32_t)__bfloat16_as_ushort(h1) << 16) | __bfloat16_as_ushort(h0);
    lp = ((uint32_t)__bfloat16_as_ushort(l1) << 16) | __bfloat16_as_ushort(l0);
}

#define STRIDE_B 272u
#define A_BYTES  17408u
#define SMEM_TOTAL (2 * 17408 + 69632)   // 104448

// ---------------------------------------------------------------------------
// Stage loaders + mainloop
// ---------------------------------------------------------------------------
__device__ __forceinline__ void store_a_pair(uint32_t AH, uint32_t AL,
                                             uint32_t off, const float4& v) {
    uint32_t h01, l01, h23, l23;
    split_pack(v.x, v.y, h01, l01);
    split_pack(v.z, v.w, h23, l23);
    asm volatile("st.shared.v2.b32 [%0], {%1,%2};"
                 :: "r"(AH + off), "r"(h01), "r"(h23) : "memory");
    asm volatile("st.shared.v2.b32 [%0], {%1,%2};"
                 :: "r"(AL + off), "r"(l01), "r"(l23) : "memory");
}

__device__ __forceinline__ void load_A_direct(const float* __restrict__ A,
                                              int row0, int M,
                                              uint32_t AH, uint32_t AL, int tid) {
#pragma unroll
    for (int i = 0; i < 8; i++) {
        int idx = tid + i * 256;
        int r  = idx >> 5;
        int c4 = idx & 31;
        float4 v = make_float4(0.f, 0.f, 0.f, 0.f);
        if (row0 + r < M)
            v = *(const float4*)(A + (size_t)(row0 + r) * 128 + c4 * 4);
        store_a_pair(AH, AL, (uint32_t)r * STRIDE_B + (uint32_t)c4 * 8, v);
    }
}

// fp16 row load: lane reads 4 halfs (8B); full row = 256B coalesced.
__device__ __forceinline__ float4 row_load128h(const __half* __restrict__ x,
                                               int s, int lane) {
    uint2 u = *(const uint2*)(x + (size_t)s * 128 + lane * 4);
    __half2 h0 = *reinterpret_cast<__half2*>(&u.x);
    __half2 h1 = *reinterpret_cast<__half2*>(&u.y);
    float2 f0 = __half22float2(h0);
    float2 f1 = __half22float2(h1);
    return make_float4(f0.x, f0.y, f1.x, f1.y);
}

// 4-wide tail for one row (fp16 source).
__device__ __forceinline__ void gather_tail128(const __half* __restrict__ x,
                                               const int* __restrict__ csr,
                                               int st, int& j, int dg,
                                               int lane, float4& a) {
    for (; j + 4 <= dg; j += 4) {
        int s0 = csr[st + j],     s1 = csr[st + j + 1];
        int s2 = csr[st + j + 2], s3 = csr[st + j + 3];
        float4 v0 = row_load128h(x, s0, lane);
        float4 v1 = row_load128h(x, s1, lane);
        float4 v2 = row_load128h(x, s2, lane);
        float4 v3 = row_load128h(x, s3, lane);
        a.x += (v0.x + v1.x) + (v2.x + v3.x);
        a.y += (v0.y + v1.y) + (v2.y + v3.y);
        a.z += (v0.z + v1.z) + (v2.z + v3.z);
        a.w += (v0.w + v1.w) + (v2.w + v3.w);
    }
    if (j + 2 <= dg) {
        int s0 = csr[st + j], s1 = csr[st + j + 1];
        float4 v0 = row_load128h(x, s0, lane);
        float4 v1 = row_load128h(x, s1, lane);
        a.x += v0.x + v1.x; a.y += v0.y + v1.y;
        a.z += v0.z + v1.z; a.w += v0.w + v1.w;
        j += 2;
    }
    if (j < dg) {
        float4 v = row_load128h(x, csr[st + j], lane);
        a.x += v.x; a.y += v.y; a.z += v.z; a.w += v.w;
        j++;
    }
}

// CSR mean-gather from fp16-staged features; pairwise-interleaved rows.
__device__ __forceinline__ void load_A_gather(const __half* __restrict__ x,
                                              const int* __restrict__ off,
                                              const int* __restrict__ cnt,
                                              const int* __restrict__ csr,
                                              int row0, int M,
                                              uint32_t AH, uint32_t AL,
                                              int wid, int lane) {
#pragma unroll
    for (int p = 0; p < 4; p++) {
        int rA  = wid + (2 * p) * 8;
        int rB  = rA + 8;
        int grA = row0 + rA;
        int grB = row0 + rB;
        float4 aA = make_float4(0.f, 0.f, 0.f, 0.f);
        float4 aB = make_float4(0.f, 0.f, 0.f, 0.f);
        int stA = 0, dgA = 0, stB = 0, dgB = 0;
        if (grA < M) { stA = off[grA]; dgA = cnt[grA]; }
        if (grB < M) { stB = off[grB]; dgB = cnt[grB]; }
        int ja = 0, jb = 0;
        while (ja + 4 <= dgA && jb + 4 <= dgB) {
            int a0 = csr[stA + ja],     a1 = csr[stA + ja + 1];
            int a2 = csr[stA + ja + 2], a3 = csr[stA + ja + 3];
            int b0 = csr[stB + jb],     b1 = csr[stB + jb + 1];
            int b2 = csr[stB + jb + 2], b3 = csr[stB + jb + 3];
            float4 va0 = row_load128h(x, a0, lane);
            float4 va1 = row_load128h(x, a1, lane);
            float4 va2 = row_load128h(x, a2, lane);
            float4 va3 = row_load128h(x, a3, lane);
            float4 vb0 = row_load128h(x, b0, lane);
            float4 vb1 = row_load128h(x, b1, lane);
            float4 vb2 = row_load128h(x, b2, lane);
            float4 vb3 = row_load128h(x, b3, lane);
            aA.x += (va0.x + va1.x) + (va2.x + va3.x);
            aA.y += (va0.y + va1.y) + (va2.y + va3.y);
            aA.z += (va0.z + va1.z) + (va2.z + va3.z);
            aA.w += (va0.w + va1.w) + (va2.w + va3.w);
            aB.x += (vb0.x + vb1.x) + (vb2.x + vb3.x);
            aB.y += (vb0.y + vb1.y) + (vb2.y + vb3.y);
            aB.z += (vb0.z + vb1.z) + (vb2.z + vb3.z);
            aB.w += (vb0.w + vb1.w) + (vb2.w + vb3.w);
            ja += 4; jb += 4;
        }
        gather_tail128(x, csr, stA, ja, dgA, lane, aA);
        gather_tail128(x, csr, stB, jb, dgB, lane, aB);
        {
            float inv = (dgA > 0) ? (1.0f / (float)dgA) : 0.0f;
            aA.x *= inv; aA.y *= inv; aA.z *= inv; aA.w *= inv;
            store_a_pair(AH, AL, (uint32_t)rA * STRIDE_B + (uint32_t)lane * 8, aA);
        }
        {
            float inv = (dgB > 0) ? (1.0f / (float)dgB) : 0.0f;
            aB.x *= inv; aB.y *= inv; aB.z *= inv; aB.w *= inv;
            store_a_pair(AH, AL, (uint32_t)rB * STRIDE_B + (uint32_t)lane * 8, aB);
        }
    }
}

template <int N>
__device__ __forceinline__ void load_B_async(const float* __restrict__ src,
                                             uint32_t BB, int tid) {
    constexpr int T4 = (2 * N * 136 * 2) / 16;
#pragma unroll
    for (int i = tid; i < T4; i += 256) {
        asm volatile("cp.async.cg.shared.global [%0], [%1], 16;"
                     :: "r"(BB + (uint32_t)i * 16), "l"(src + (size_t)i * 4)
                     : "memory");
    }
}
__device__ __forceinline__ void cp_commit() {
    asm volatile("cp.async.commit_group;" ::: "memory");
}
__device__ __forceinline__ void cp_wait_all() {
    asm volatile("cp.async.wait_group 0;" ::: "memory");
}

template <int N>
__device__ __forceinline__ void mainloop(uint32_t AH, uint32_t AL,
                                         uint32_t BH, uint32_t BL,
                                         float (*acc)[4],
                                         int a_row, int a_kof,
                                         int b_nof, int b_kof, int wcg) {
    constexpr int NOCT = N / 16;
#pragma unroll
    for (int k0 = 0; k0 < 128; k0 += 16) {
        uint32_t ah[4], al[4];
        uint32_t aoff = (uint32_t)a_row * STRIDE_B + (uint32_t)(k0 + a_kof) * 2;
        LDSM_X4(ah[0], ah[1], ah[2], ah[3], AH + aoff);
        LDSM_X4(al[0], al[1], al[2], al[3], AL + aoff);
#pragma unroll
        for (int op = 0; op < NOCT; op += 2) {
            int nbase = wcg * (N / 2) + op * 8;
            uint32_t boff = (uint32_t)(nbase + b_nof) * STRIDE_B
                          + (uint32_t)(k0 + b_kof) * 2;
            uint32_t bh0, bh1, bh2, bh3, bl0, bl1, bl2, bl3;
            LDSM_X4(bh0, bh1, bh2, bh3, BH + boff);
            LDSM_X4(bl0, bl1, bl2, bl3, BL + boff);
            mma_bf16(acc[op],     ah, bh0, bh1);
            mma_bf16(acc[op],     al, bh0, bh1);
            mma_bf16(acc[op],     ah, bl0, bl1);
            mma_bf16(acc[op + 1], ah, bh2, bh3);
            mma_bf16(acc[op + 1], al, bh2, bh3);
            mma_bf16(acc[op + 1], ah, bl2, bl3);
        }
    }
}

// ---------------------------------------------------------------------------
// Small kernels: counts / CSR build / fp16 staging
// ---------------------------------------------------------------------------
__global__ void count3_kernel(const int* __restrict__ d0,
                              const int* __restrict__ d1,
                              const int* __restrict__ d2,
                              int* __restrict__ cnt, int E) {
    int i = blockIdx.x * blockDim.x + threadIdx.x;
    if (i < E) atomicAdd(&cnt[d0[i]], 1);
    else if (i < 2 * E) atomicAdd(&cnt[N_ROBOT + d1[i - E]], 1);
    else if (i < 3 * E) atomicAdd(&cnt[2 * N_ROBOT + d2[i - 2 * E]], 1);
}

__global__ void fill3_csr_kernel(const int* __restrict__ s0, const int* __restrict__ d0,
                                 const int* __restrict__ s1, const int* __restrict__ d1,
                                 const int* __restrict__ s2, const int* __restrict__ d2,
                                 int* __restrict__ cursor,
                                 int* __restrict__ csr, int E) {
    int i = blockIdx.x * blockDim.x + threadIdx.x;
    int pos;
    if (i < E) {
        pos = atomicAdd(&cursor[d0[i]], 1);
        csr[pos] = s0[i];
    } else if (i < 2 * E) {
        pos = atomicAdd(&cursor[N_ROBOT + d1[i - E]], 1);
        csr[pos] = s1[i - E];
    } else if (i < 3 * E) {
        pos = atomicAdd(&cursor[2 * N_ROBOT + d2[i - 2 * E]], 1);
        csr[pos] = s2[i - 2 * E];
    }
}

// fp32 -> fp16 feature staging (both node tensors, one launch).
__global__ void stage_x_kernel(const float* __restrict__ xr,
                               const float* __restrict__ xb,
                               __half* __restrict__ xhr,
                               __half* __restrict__ xhb) {
    const int CH = (N_ROBOT * 128) / 4;   // float4 chunks per tensor: 3.2M
    int i = blockIdx.x * blockDim.x + threadIdx.x;
    const float* src;
    __half* dst;
    int c;
    if (i < CH) { src = xr; dst = xhr; c = i; }
    else if (i < 2 * CH) { src = xb; dst = xhb; c = i - CH; }
    else return;
    float4 v = ((const float4*)src)[c];
    __half2 h0 = __floats2half2_rn(v.x, v.y);
    __half2 h1 = __floats2half2_rn(v.z, v.w);
    uint2 u;
    u.x = *reinterpret_cast<uint32_t*>(&h0);
    u.y = *reinterpret_cast<uint32_t*>(&h1);
    ((uint2*)dst)[c] = u;
}

__global__ void scan1_kernel(const int* __restrict__ cnt,
                             int* __restrict__ out, int* __restrict__ bsum) {
    __shared__ int sh[SCAN_BS];
    int gid = blockIdx.x * SCAN_BS + threadIdx.x;
    int v = (gid < NSCAN) ? cnt[gid] : 0;
    sh[threadIdx.x] = v;
    __syncthreads();
#pragma unroll
    for (int d = 1; d < SCAN_BS; d <<= 1) {
        int t = (threadIdx.x >= d) ? sh[threadIdx.x - d] : 0;
        __syncthreads();
        sh[threadIdx.x] += t;
        __syncthreads();
    }
    if (gid < NSCAN) out[gid] = sh[threadIdx.x] - v;
    if (threadIdx.x == SCAN_BS - 1) bsum[blockIdx.x] = sh[threadIdx.x];
}

__global__ void scan2_kernel(int* __restrict__ bsum) {
    __shared__ int sh[1024];
    int i = threadIdx.x;
    int v = (i < SCAN_NB) ? bsum[i] : 0;
    sh[i] = v;
    __syncthreads();
#pragma unroll
    for (int d = 1; d < 1024; d <<= 1) {
        int t = (i >= d) ? sh[i - d] : 0;
        __syncthreads();
        sh[i] += t;
        __syncthreads();
    }
    if (i < SCAN_NB) bsum[i] = sh[i] - v;
}

__global__ void scan3_kernel(int* __restrict__ out, const int* __restrict__ bsum,
                             int* __restrict__ cursor) {
    int gid = blockIdx.x * SCAN_BS + threadIdx.x;
    if (gid < NSCAN) {
        int o = out[gid] + bsum[blockIdx.x];
        out[gid] = o;
        cursor[gid] = o;
    }
}

// ---------------------------------------------------------------------------
// Unified prep kernel: 8 weight splits + 2 bias folds in ONE launch.
// ---------------------------------------------------------------------------
__device__ __forceinline__ void split_one(const float* __restrict__ A,
                                          const float* __restrict__ B2,
                                          float* __restrict__ outf,
                                          int N, int e) {
    if (e >= 128 * N) return;
    int k = e / N;
    int n = e - k * N;
    float w = A[e];
    if (B2) w += B2[e];
    __nv_bfloat16 h = __float2bfloat16(w);
    __nv_bfloat16 l = __float2bfloat16(w - __bfloat162float(h));
    __nv_bfloat16* out = (__nv_bfloat16*)outf;
    out[n * 136 + k] = h;
    out[(size_t)N * 136 + n * 136 + k] = l;
}

__global__ void prep_kernel(const float* __restrict__ Wl0_rr,
                            const float* __restrict__ Wl0_br,
                            const float* __restrict__ Wr0_rr,
                            const float* __restrict__ Wr0_br,
                            const float* __restrict__ Wl0_rb,
                            const float* __restrict__ Wr0_rb,
                            const float* __restrict__ Wl1_rr,
                            const float* __restrict__ Wr1_rr,
                            const float* __restrict__ Wr1_br,
                            const float* __restrict__ Wl1_br,
                            const float* __restrict__ b0_rr,
                            const float* __restrict__ b0_br,
                            const float* __restrict__ b1_rr,
                            const float* __restrict__ b1_br,
                            float* __restrict__ WB0_rr,
                            float* __restrict__ WB0_br,
                            float* __restrict__ WBsum0,
                            float* __restrict__ WB0_rb,
                            float* __restrict__ WBr0_rb,
                            float* __restrict__ WB1_rr,
                            float* __restrict__ WBsum1,
                            float* __restrict__ WB1_br,
                            float* __restrict__ bsum0,
                            float* __restrict__ bsum1) {
    int b = blockIdx.x;
    int t = threadIdx.x;
    if (b < 320) {
        int seg = b >> 6;
        int e = (b & 63) * 256 + t;
        switch (seg) {
            case 0: split_one(Wl0_rr, nullptr, WB0_rr, 128, e); break;
            case 1: split_one(Wl0_br, nullptr, WB0_br, 128, e); break;
            case 2: split_one(Wr0_rr, Wr0_br, WBsum0, 128, e); break;
            case 3: split_one(Wl0_rb, nullptr, WB0_rb, 128, e); break;
            default: split_one(Wr0_rb, nullptr, WBr0_rb, 128, e); break;
        }
    } else if (b < 416) {
        int seg = (b - 320) >> 5;
        int e = ((b - 320) & 31) * 256 + t;
        switch (seg) {
            case 0: split_one(Wl1_rr, nullptr, WB1_rr, 64, e); break;
            case 1: split_one(Wr1_rr, Wr1_br, WBsum1, 64, e); break;
            default: split_one(Wl1_br, nullptr, WB1_br, 64, e); break;
        }
    } else {
        if (t < 128) bsum0[t] = b0_rr[t] + b0_br[t];
        else if (t < 192) bsum1[t - 128] = b1_rr[t - 128] + b1_br[t - 128];
    }
}

// ---------------------------------------------------------------------------
// Unified fused GEMM kernel
// ---------------------------------------------------------------------------
__global__ void __launch_bounds__(256, 2)
fused_kernel(const float* __restrict__ x_robot,
             const float* __restrict__ x_ball,
             const __half* __restrict__ xh_robot,
             const __half* __restrict__ xh_ball,
             const int* __restrict__ off, const int* __restrict__ cnt,
             const int* __restrict__ csr,
             const float* __restrict__ WB0_rr,
             const float* __restrict__ WB0_br,
             const float* __restrict__ WBsum0,
             const float* __restrict__ bsum0,
             const float* __restrict__ WB1_rr,
             const float* __restrict__ WBsum1,
             const float* __restrict__ WB0_rb,
             const float* __restrict__ WBr0_rb,
             const float* __restrict__ b0_rb,
             const float* __restrict__ WB1_br,
             float* __restrict__ t_rr,
             float* __restrict__ f_r,
             float* __restrict__ t_br) {
    extern __shared__ char smem[];
    const uint32_t AH = smem_u32(smem);
    const uint32_t AL = AH + A_BYTES;
    const uint32_t BB = AL + A_BYTES;

    const int tid  = threadIdx.x;
    const int wid  = tid >> 5;
    const int lane = tid & 31;
    const int wr   = wid & 3;
    const int wcg  = wid >> 2;

    const int a_row = wr * 16 + ((lane >> 3) & 1) * 8 + (lane & 7);
    const int a_kof = (lane >> 4) * 8;
    const int b_nof = ((lane >> 4) & 1) * 8 + (lane & 7);
    const int b_kof = ((lane >> 3) & 1) * 8;

    float acc[8][4];
#pragma unroll
    for (int o = 0; o < 8; o++)
#pragma unroll
        for (int j = 0; j < 4; j++) acc[o][j] = 0.0f;

    const bool robot = (blockIdx.x < GB_ROBOT);

    if (robot) {
        const int row0 = blockIdx.x * 64;
        const int M    = N_ROBOT;

        load_B_async<128>(WB0_rr, BB, tid);
        cp_commit();
        load_A_gather(xh_robot, off, cnt, csr, row0, M, AH, AL, wid, lane);
        cp_wait_all();
        __syncthreads();
        mainloop<128>(AH, AL, BB, BB + 34816, acc, a_row, a_kof, b_nof, b_kof, wcg);
        __syncthreads();
        load_B_async<128>(WB0_br, BB, tid);
        cp_commit();
        load_A_gather(xh_ball, off + N_ROBOT, cnt + N_ROBOT, csr, row0, M, AH, AL, wid, lane);
        cp_wait_all();
        __syncthreads();
        mainloop<128>(AH, AL, BB, BB + 34816, acc, a_row, a_kof, b_nof, b_kof, wcg);
        __syncthreads();
        load_B_async<128>(WBsum0, BB, tid);
        cp_commit();
        load_A_direct(x_robot, row0, M, AH, AL, tid);
        cp_wait_all();
        __syncthreads();
        mainloop<128>(AH, AL, BB, BB + 34816, acc, a_row, a_kof, b_nof, b_kof, wcg);
        __syncthreads();

        load_B_async<64>(WB1_rr, BB, tid);
        load_B_async<64>(WBsum1, BB + 2 * 17408, tid);
        cp_commit();

        {
            const int rAl = wr * 16 + (lane >> 2);
            const int rBl = rAl + 8;
#pragma unroll
            for (int o = 0; o < 8; o++) {
                int col = wcg * 64 + o * 8 + (lane & 3) * 2;
                float2 bv = *(const float2*)(bsum0 + col);
                float v0 = fmaxf(acc[o][0] + bv.x, 0.f);
                float v1 = fmaxf(acc[o][1] + bv.y, 0.f);
                float v2 = fmaxf(acc[o][2] + bv.x, 0.f);
                float v3 = fmaxf(acc[o][3] + bv.y, 0.f);
                uint32_t h, l;
                uint32_t offA = (uint32_t)rAl * STRIDE_B + (uint32_t)col * 2;
                split_pack(v0, v1, h, l);
                asm volatile("st.shared.b32 [%0], %1;" :: "r"(AH + offA), "r"(h) : "memory");
                asm volatile("st.shared.b32 [%0], %1;" :: "r"(AL + offA), "r"(l) : "memory");
                uint32_t offB = (uint32_t)rBl * STRIDE_B + (uint32_t)col * 2;
                split_pack(v2, v3, h, l);
                asm volatile("st.shared.b32 [%0], %1;" :: "r"(AH + offB), "r"(h) : "memory");
                asm volatile("st.shared.b32 [%0], %1;" :: "r"(AL + offB), "r"(l) : "memory");
            }
        }
        cp_wait_all();
        __syncthreads();

        float acc2a[4][4], acc2b[4][4];
#pragma unroll
        for (int o = 0; o < 4; o++)
#pragma unroll
            for (int j = 0; j < 4; j++) { acc2a[o][j] = 0.f; acc2b[o][j] = 0.f; }

        mainloop<64>(AH, AL, BB,             BB + 17408,     acc2a,
                     a_row, a_kof, b_nof, b_kof, wcg);
        mainloop<64>(AH, AL, BB + 2 * 17408, BB + 3 * 17408, acc2b,
                     a_row, a_kof, b_nof, b_kof, wcg);

        const int rA = row0 + wr * 16 + (lane >> 2);
        const int rB = rA + 8;
#pragma unroll
        for (int o = 0; o < 4; o++) {
            int col = wcg * 32 + o * 8 + (lane & 3) * 2;
            if (rA < M) {
                *(float2*)(t_rr + (size_t)rA * 64 + col) = make_float2(acc2a[o][0], acc2a[o][1]);
                *(float2*)(f_r  + (size_t)rA * 64 + col) = make_float2(acc2b[o][0], acc2b[o][1]);
            }
            if (rB < M) {
                *(float2*)(t_rr + (size_t)rB * 64 + col) = make_float2(acc2a[o][2], acc2a[o][3]);
                *(float2*)(f_r  + (size_t)rB * 64 + col) = make_float2(acc2b[o][2], acc2b[o][3]);
            }
        }
    } else {
        const int row0 = (blockIdx.x - GB_ROBOT) * 64;
        const int M    = N_BALL;

        load_B_async<128>(WB0_rb, BB, tid);
        cp_commit();
        load_A_gather(xh_robot, off + 2 * N_ROBOT, cnt + 2 * N_ROBOT, csr,
                      row0, M, AH, AL, wid, lane);
        cp_wait_all();
        __syncthreads();
        mainloop<128>(AH, AL, BB, BB + 34816, acc, a_row, a_kof, b_nof, b_kof, wcg);
        __syncthreads();
        load_B_async<128>(WBr0_rb, BB, tid);
        cp_commit();
        load_A_direct(x_ball, row0, M, AH, AL, tid);
        cp_wait_all();
        __syncthreads();
        mainloop<128>(AH, AL, BB, BB + 34816, acc, a_row, a_kof, b_nof, b_kof, wcg);
        __syncthreads();

        load_B_async<64>(WB1_br, BB, tid);
        cp_commit();
        {
            const int rAl = wr * 16 + (lane >> 2);
            const int rBl = rAl + 8;
#pragma unroll
            for (int o = 0; o < 8; o++) {
                int col = wcg * 64 + o * 8 + (lane & 3) * 2;
                float2 bv = *(const float2*)(b0_rb + col);
                float v0 = fmaxf(acc[o][0] + bv.x, 0.f);
                float v1 = fmaxf(acc[o][1] + bv.y, 0.f);
                float v2 = fmaxf(acc[o][2] + bv.x, 0.f);
                float v3 = fmaxf(acc[o][3] + bv.y, 0.f);
                uint32_t h, l;
                uint32_t offA = (uint32_t)rAl * STRIDE_B + (uint32_t)col * 2;
                split_pack(v0, v1, h, l);
                asm volatile("st.shared.b32 [%0], %1;" :: "r"(AH + offA), "r"(h) : "memory");
                asm volatile("st.shared.b32 [%0], %1;" :: "r"(AL + offA), "r"(l) : "memory");
                uint32_t offB = (uint32_t)rBl * STRIDE_B + (uint32_t)col * 2;
                split_pack(v2, v3, h, l);
                asm volatile("st.shared.b32 [%0], %1;" :: "r"(AH + offB), "r"(h) : "memory");
                asm volatile("st.shared.b32 [%0], %1;" :: "r"(AL + offB), "r"(l) : "memory");
            }
        }
        cp_wait_all();
        __syncthreads();

        float acc2[4][4];
#pragma unroll
        for (int o = 0; o < 4; o++)
#pragma unroll
            for (int j = 0; j < 4; j++) acc2[o][j] = 0.f;

        mainloop<64>(AH, AL, BB, BB + 17408, acc2, a_row, a_kof, b_nof, b_kof, wcg);

        const int rA = row0 + wr * 16 + (lane >> 2);
        const int rB = rA + 8;
#pragma unroll
        for (int o = 0; o < 4; o++) {
            int col = wcg * 32 + o * 8 + (lane & 3) * 2;
            if (rA < M)
                *(float2*)(t_br + (size_t)rA * 64 + col) = make_float2(acc2[o][0], acc2[o][1]);
            if (rB < M)
                *(float2*)(t_br + (size_t)rB * 64 + col) = make_float2(acc2[o][2], acc2[o][3]);
        }
    }
}

// ---------------------------------------------------------------------------
// Final: out[d] = mean_rr(t_rr) + mean_br(t_br) + f_r[d] + bsum1
// ---------------------------------------------------------------------------
__device__ __forceinline__ float2 row_load64(const float* __restrict__ t,
                                             int s, int lane) {
    return *(const float2*)(t + (size_t)s * 64 + lane * 2);
}

__device__ __forceinline__ void tail64(const float* __restrict__ t,
                                       const int* __restrict__ csr,
                                       int st, int& j, int dg,
                                       int lane, float2& a) {
    for (; j + 4 <= dg; j += 4) {
        int s0 = csr[st + j], s1 = csr[st + j + 1];
        int s2 = csr[st + j + 2], s3 = csr[st + j + 3];
        float2 v0 = row_load64(t, s0, lane);
        float2 v1 = row_load64(t, s1, lane);
        float2 v2 = row_load64(t, s2, lane);
        float2 v3 = row_load64(t, s3, lane);
        a.x += (v0.x + v1.x) + (v2.x + v3.x);
        a.y += (v0.y + v1.y) + (v2.y + v3.y);
    }
    if (j + 2 <= dg) {
        int s0 = csr[st + j], s1 = csr[st + j + 1];
        float2 v0 = row_load64(t, s0, lane);
        float2 v1 = row_load64(t, s1, lane);
        a.x += v0.x + v1.x; a.y += v0.y + v1.y;
        j += 2;
    }
    if (j < dg) {
        float2 v = row_load64(t, csr[st + j], lane);
        a.x += v.x; a.y += v.y;
    }
}

__global__ void __launch_bounds__(256)
final_kernel(const int* __restrict__ off_rr, const int* __restrict__ cnt_rr,
             const int* __restrict__ off_br, const int* __restrict__ cnt_br,
             const int* __restrict__ csr,
             const float* __restrict__ t_rr, const float* __restrict__ t_br,
             const float* __restrict__ f_r, const float* __restrict__ bsum1,
             float* __restrict__ out) {
    int warp = (blockIdx.x * blockDim.x + threadIdx.x) >> 5;
    int lane = threadIdx.x & 31;
    if (warp >= N_ROBOT) return;

    float2 res = *(const float2*)(f_r + (size_t)warp * 64 + lane * 2);
    float2 bv  = *(const float2*)(bsum1 + lane * 2);
    res.x += bv.x; res.y += bv.y;

    int st0 = off_rr[warp], dg0 = cnt_rr[warp];
    int st1 = off_br[warp], dg1 = cnt_br[warp];
    float2 a0 = make_float2(0.f, 0.f);
    float2 a1 = make_float2(0.f, 0.f);
    int j0 = 0, j1 = 0;
    while (j0 + 4 <= dg0 && j1 + 4 <= dg1) {
        int r0 = csr[st0 + j0],     r1 = csr[st0 + j0 + 1];
        int r2 = csr[st0 + j0 + 2], r3 = csr[st0 + j0 + 3];
        int b0 = csr[st1 + j1],     b1 = csr[st1 + j1 + 1];
        int b2 = csr[st1 + j1 + 2], b3 = csr[st1 + j1 + 3];
        float2 u0 = row_load64(t_rr, r0, lane);
        float2 u1 = row_load64(t_rr, r1, lane);
        float2 u2 = row_load64(t_rr, r2, lane);
        float2 u3 = row_load64(t_rr, r3, lane);
        float2 w0 = row_load64(t_br, b0, lane);
        float2 w1 = row_load64(t_br, b1, lane);
        float2 w2 = row_load64(t_br, b2, lane);
        float2 w3 = row_load64(t_br, b3, lane);
        a0.x += (u0.x + u1.x) + (u2.x + u3.x);
        a0.y += (u0.y + u1.y) + (u2.y + u3.y);
        a1.x += (w0.x + w1.x) + (w2.x + w3.x);
        a1.y += (w0.y + w1.y) + (w2.y + w3.y);
        j0 += 4; j1 += 4;
    }
    tail64(t_rr, csr, st0, j0, dg0, lane, a0);
    tail64(t_br, csr, st1, j1, dg1, lane, a1);

    float inv0 = (dg0 > 0) ? (1.0f / (float)dg0) : 0.0f;
    float inv1 = (dg1 > 0) ? (1.0f / (float)dg1) : 0.0f;
    res.x += a0.x * inv0 + a1.x * inv1;
    res.y += a0.y * inv0 + a1.y * inv1;

    *(float2*)(out + (size_t)warp * 64 + lane * 2) = res;
}

// ---------------------------------------------------------------------------
// Launch
// ---------------------------------------------------------------------------
extern "C" void kernel_launch(void* const* d_in, const int* in_sizes, int n_in,
                              void* d_out, int out_size) {
    (void)n_in; (void)out_size;

    const float* x_robot = (const float*)d_in[0];
    const float* x_ball  = (const float*)d_in[1];
    const int* ei_rr = (const int*)d_in[2];
    const int* ei_rb = (const int*)d_in[3];
    const int* ei_br = (const int*)d_in[4];
    const float* Wl0_rr = (const float*)d_in[5];
    const float* Wr0_rr = (const float*)d_in[6];
    const float* b0_rr  = (const float*)d_in[7];
    const float* Wl0_rb = (const float*)d_in[8];
    const float* Wr0_rb = (const float*)d_in[9];
    const float* b0_rb  = (const float*)d_in[10];
    const float* Wl0_br = (const float*)d_in[11];
    const float* Wr0_br = (const float*)d_in[12];
    const float* b0_br  = (const float*)d_in[13];
    const float* Wl1_rr = (const float*)d_in[14];
    const float* Wr1_rr = (const float*)d_in[15];
    const float* b1_rr  = (const float*)d_in[16];
    const float* Wl1_br = (const float*)d_in[20];
    const float* Wr1_br = (const float*)d_in[21];
    const float* b1_br  = (const float*)d_in[22];

    float* out = (float*)d_out;
    const int E = in_sizes[2] / 2;

    float* S = nullptr;
    int *C = nullptr, *OFF = nullptr, *CUR = nullptr, *CSR = nullptr, *BS = nullptr;
    {
        void* p = nullptr;
        cudaGetSymbolAddress(&p, g_scratch); S = (float*)p;
        cudaGetSymbolAddress(&p, g_cnt);     C = (int*)p;
        cudaGetSymbolAddress(&p, g_off);     OFF = (int*)p;
        cudaGetSymbolAddress(&p, g_cursor);  CUR = (int*)p;
        cudaGetSymbolAddress(&p, g_csr);     CSR = (int*)p;
        cudaGetSymbolAddress(&p, g_bsum);    BS = (int*)p;
    }

    float* t_rr    = S + O_TRR;
    float* t_br    = S + O_TBR;
    float* f_r     = S + O_FR;
    float* bsum0   = S + O_BSUM0;
    float* bsum1   = S + O_BSUM1;
    float* WB0_rr  = S + O_WB0_RR;
    float* WB0_br  = S + O_WB0_BR;
    float* WBsum0  = S + O_WBSUM0;
    float* WB0_rb  = S + O_WB0_RB;
    float* WBr0_rb = S + O_WBR0_RB;
    float* WB1_rr  = S + O_WB1_RR;
    float* WBsum1  = S + O_WBSUM1;
    float* WB1_br  = S + O_WB1_BR;
    __half* xh_robot = (__half*)(S + O_XH_R);
    __half* xh_ball  = (__half*)(S + O_XH_B);

    cudaFuncSetAttribute(fused_kernel,
                         cudaFuncAttributeMaxDynamicSharedMemorySize, SMEM_TOTAL);

    // ---- fp16 feature staging + counts ----
    cudaMemsetAsync(C, 0, 3ull * N_ROBOT * sizeof(int), 0);
    {
        const int CH = (N_ROBOT * 128) / 4;             // 3.2M chunks each
        stage_x_kernel<<<(2 * CH + 255) / 256, 256>>>(x_robot, x_ball,
                                                      xh_robot, xh_ball);
    }
    const int cb3 = (3 * E + 255) / 256;
    count3_kernel<<<cb3, 256>>>(ei_rr + E, ei_br + E, ei_rb + E, C, E);

    // ---- CSR build ----
    scan1_kernel<<<SCAN_NB, SCAN_BS>>>(C, OFF, BS);
    scan2_kernel<<<1, 1024>>>(BS);
    scan3_kernel<<<SCAN_NB, SCAN_BS>>>(OFF, BS, CUR);
    fill3_csr_kernel<<<cb3, 256>>>(ei_rr, ei_rr + E, ei_br, ei_br + E,
                                   ei_rb, ei_rb + E, CUR, CSR, E);

    // ---- unified weight/bias prep ----
    prep_kernel<<<417, 256>>>(Wl0_rr, Wl0_br, Wr0_rr, Wr0_br, Wl0_rb, Wr0_rb,
                              Wl1_rr, Wr1_rr, Wr1_br, Wl1_br,
                              b0_rr, b0_br, b1_rr, b1_br,
                              WB0_rr, WB0_br, WBsum0, WB0_rb, WBr0_rb,
                              WB1_rr, WBsum1, WB1_br, bsum0, bsum1);

    // ---- unified fused compute ----
    fused_kernel<<<GB_ROBOT + GB_BALL, 256, SMEM_TOTAL>>>(
        x_robot, x_ball, xh_robot, xh_ball, OFF, C, CSR,
        WB0_rr, WB0_br, WBsum0, bsum0, WB1_rr, WBsum1,
        WB0_rb, WBr0_rb, b0_rb, WB1_br,
        t_rr, f_r, t_br);

    // ---- final combine ----
    const int fb = (N_ROBOT * 32 + 255) / 256;
    final_kernel<<<fb, 256>>>(OFF, C, OFF + N_ROBOT, C + N_ROBOT, CSR,
                              t_rr, t_br, f_r, bsum1, out);
}

// round 14
// speedup vs baseline: 1.0328x; 1.0328x over previous
#include <cuda_runtime.h>
#include <cuda_bf16.h>
#include <stdint.h>

// ---------------------------------------------------------------------------
// Problem constants
// ---------------------------------------------------------------------------
#define N_ROBOT 100000
#define N_BALL  100000
#define E_MAX   600000
#define GB_ROBOT ((N_ROBOT + 63) / 64)   // 1563
#define GB_BALL  ((N_BALL + 63) / 64)    // 1563

// ---------------------------------------------------------------------------
// Scratch (device globals; allocation is forbidden)
// ---------------------------------------------------------------------------
#define O_TRR     0ull
#define O_TBR     (O_TRR + 6400000ull)
#define O_FR      (O_TBR + 6400000ull)
#define O_BSUM0   (O_FR  + 6400000ull)
#define O_BSUM1   (O_BSUM0 + 128ull)
#define O_WB0_RR  (O_BSUM1 + 64ull)
#define O_WB0_BR  (O_WB0_RR + 17408ull)
#define O_WBSUM0  (O_WB0_BR + 17408ull)
#define O_WB0_RB  (O_WBSUM0 + 17408ull)
#define O_WBR0_RB (O_WB0_RB + 17408ull)
#define O_WB1_RR  (O_WBR0_RB + 17408ull)
#define O_WBSUM1  (O_WB1_RR + 8704ull)
#define O_WB1_BR  (O_WBSUM1 + 8704ull)
#define SCRATCH_FLOATS (O_WB1_BR + 8704ull)

__device__ float g_scratch[SCRATCH_FLOATS];
// counts (3*N_ROBOT) + lookback state (2048 ints = 1024 ULLs), one memset covers all
__device__ int   g_cnt[3 * N_ROBOT + 2048];
__device__ int   g_off[3 * N_ROBOT];
__device__ int   g_cursor[3 * N_ROBOT];
__device__ int   g_csr[3 * E_MAX + 64];

#define NSCAN   (3 * N_ROBOT)
#define SCAN_BS 512
#define SCAN_NB ((NSCAN + SCAN_BS - 1) / SCAN_BS)   // 586
#define PREP_NB 209
#define FLAG_A  (1ull << 62)
#define FLAG_P  (1ull << 63)
#define VALMASK 0xFFFFFFFFull

// ---------------------------------------------------------------------------
// Helpers (baseline PTX only)
// ---------------------------------------------------------------------------
__device__ __forceinline__ uint32_t smem_u32(const void* p) {
    uint32_t a;
    asm("{ .reg .u64 t; cvta.to.shared.u64 t, %1; cvt.u32.u64 %0, t; }"
        : "=r"(a) : "l"(p));
    return a;
}

#define LDSM_X4(r0, r1, r2, r3, addr) \
    asm volatile("ldmatrix.sync.aligned.m8n8.x4.shared.b16 {%0,%1,%2,%3}, [%4];" \
                 : "=r"(r0), "=r"(r1), "=r"(r2), "=r"(r3) : "r"(addr))

__device__ __forceinline__ void mma_bf16(float* c, const uint32_t* a,
                                         uint32_t b0, uint32_t b1) {
    asm volatile(
        "mma.sync.aligned.m16n8k16.row.col.f32.bf16.bf16.f32 "
        "{%0,%1,%2,%3}, {%4,%5,%6,%7}, {%8,%9}, {%0,%1,%2,%3};"
        : "+f"(c[0]), "+f"(c[1]), "+f"(c[2]), "+f"(c[3])
        : "r"(a[0]), "r"(a[1]), "r"(a[2]), "r"(a[3]), "r"(b0), "r"(b1));
}

__device__ __forceinline__ void split_pack(float x0, float x1,
                                           uint32_t& hp, uint32_t& lp) {
    __nv_bfloat16 h0 = __float2bfloat16(x0);
    __nv_bfloat16 h1 = __float2bfloat16(x1);
    __nv_bfloat16 l0 = __float2bfloat16(x0 - __bfloat162float(h0));
    __nv_bfloat16 l1 = __float2bfloat16(x1 - __bfloat162float(h1));
    hp = ((uint32_t)__bfloat16_as_ushort(h1) << 16) | __bfloat16_as_ushort(h0);
    lp = ((uint32_t)__bfloat16_as_ushort(l1) << 16) | __bfloat16_as_ushort(l0);
}

#define STRIDE_B 272u
#define A_BYTES  17408u
#define SMEM_TOTAL (2 * 17408 + 69632)   // 104448

// ---------------------------------------------------------------------------
// Stage loaders + mainloop
// ---------------------------------------------------------------------------
__device__ __forceinline__ void store_a_pair(uint32_t AH, uint32_t AL,
                                             uint32_t off, const float4& v) {
    uint32_t h01, l01, h23, l23;
    split_pack(v.x, v.y, h01, l01);
    split_pack(v.z, v.w, h23, l23);
    asm volatile("st.shared.v2.b32 [%0], {%1,%2};"
                 :: "r"(AH + off), "r"(h01), "r"(h23) : "memory");
    asm volatile("st.shared.v2.b32 [%0], {%1,%2};"
                 :: "r"(AL + off), "r"(l01), "r"(l23) : "memory");
}

__device__ __forceinline__ void load_A_direct(const float* __restrict__ A,
                                              int row0, int M,
                                              uint32_t AH, uint32_t AL, int tid) {
#pragma unroll
    for (int i = 0; i < 8; i++) {
        int idx = tid + i * 256;
        int r  = idx >> 5;
        int c4 = idx & 31;
        float4 v = make_float4(0.f, 0.f, 0.f, 0.f);
        if (row0 + r < M)
            v = *(const float4*)(A + (size_t)(row0 + r) * 128 + c4 * 4);
        store_a_pair(AH, AL, (uint32_t)r * STRIDE_B + (uint32_t)c4 * 8, v);
    }
}

__device__ __forceinline__ float4 row_load128(const float* __restrict__ x,
                                              int s, int lane) {
    return *(const float4*)(x + (size_t)s * 128 + lane * 4);
}

__device__ __forceinline__ void gather_tail128(const float* __restrict__ x,
                                               const int* __restrict__ csr,
                                               int st, int& j, int dg,
                                               int lane, float4& a) {
    for (; j + 4 <= dg; j += 4) {
        int s0 = csr[st + j],     s1 = csr[st + j + 1];
        int s2 = csr[st + j + 2], s3 = csr[st + j + 3];
        float4 v0 = row_load128(x, s0, lane);
        float4 v1 = row_load128(x, s1, lane);
        float4 v2 = row_load128(x, s2, lane);
        float4 v3 = row_load128(x, s3, lane);
        a.x += (v0.x + v1.x) + (v2.x + v3.x);
        a.y += (v0.y + v1.y) + (v2.y + v3.y);
        a.z += (v0.z + v1.z) + (v2.z + v3.z);
        a.w += (v0.w + v1.w) + (v2.w + v3.w);
    }
    if (j + 2 <= dg) {
        int s0 = csr[st + j], s1 = csr[st + j + 1];
        float4 v0 = row_load128(x, s0, lane);
        float4 v1 = row_load128(x, s1, lane);
        a.x += v0.x + v1.x; a.y += v0.y + v1.y;
        a.z += v0.z + v1.z; a.w += v0.w + v1.w;
        j += 2;
    }
    if (j < dg) {
        float4 v = row_load128(x, csr[st + j], lane);
        a.x += v.x; a.y += v.y; a.z += v.z; a.w += v.w;
        j++;
    }
}

// CSR mean-gather (fp32), pairwise-interleaved rows.
__device__ __forceinline__ void load_A_gather(const float* __restrict__ x,
                                              const int* __restrict__ off,
                                              const int* __restrict__ cnt,
                                              const int* __restrict__ csr,
                                              int row0, int M,
                                              uint32_t AH, uint32_t AL,
                                              int wid, int lane) {
#pragma unroll
    for (int p = 0; p < 4; p++) {
        int rA  = wid + (2 * p) * 8;
        int rB  = rA + 8;
        int grA = row0 + rA;
        int grB = row0 + rB;
        float4 aA = make_float4(0.f, 0.f, 0.f, 0.f);
        float4 aB = make_float4(0.f, 0.f, 0.f, 0.f);
        int stA = 0, dgA = 0, stB = 0, dgB = 0;
        if (grA < M) { stA = off[grA]; dgA = cnt[grA]; }
        if (grB < M) { stB = off[grB]; dgB = cnt[grB]; }
        int ja = 0, jb = 0;
        while (ja + 4 <= dgA && jb + 4 <= dgB) {
            int a0 = csr[stA + ja],     a1 = csr[stA + ja + 1];
            int a2 = csr[stA + ja + 2], a3 = csr[stA + ja + 3];
            int b0 = csr[stB + jb],     b1 = csr[stB + jb + 1];
            int b2 = csr[stB + jb + 2], b3 = csr[stB + jb + 3];
            float4 va0 = row_load128(x, a0, lane);
            float4 va1 = row_load128(x, a1, lane);
            float4 va2 = row_load128(x, a2, lane);
            float4 va3 = row_load128(x, a3, lane);
            float4 vb0 = row_load128(x, b0, lane);
            float4 vb1 = row_load128(x, b1, lane);
            float4 vb2 = row_load128(x, b2, lane);
            float4 vb3 = row_load128(x, b3, lane);
            aA.x += (va0.x + va1.x) + (va2.x + va3.x);
            aA.y += (va0.y + va1.y) + (va2.y + va3.y);
            aA.z += (va0.z + va1.z) + (va2.z + va3.z);
            aA.w += (va0.w + va1.w) + (va2.w + va3.w);
            aB.x += (vb0.x + vb1.x) + (vb2.x + vb3.x);
            aB.y += (vb0.y + vb1.y) + (vb2.y + vb3.y);
            aB.z += (vb0.z + vb1.z) + (vb2.z + vb3.z);
            aB.w += (vb0.w + vb1.w) + (vb2.w + vb3.w);
            ja += 4; jb += 4;
        }
        gather_tail128(x, csr, stA, ja, dgA, lane, aA);
        gather_tail128(x, csr, stB, jb, dgB, lane, aB);
        {
            float inv = (dgA > 0) ? (1.0f / (float)dgA) : 0.0f;
            aA.x *= inv; aA.y *= inv; aA.z *= inv; aA.w *= inv;
            store_a_pair(AH, AL, (uint32_t)rA * STRIDE_B + (uint32_t)lane * 8, aA);
        }
        {
            float inv = (dgB > 0) ? (1.0f / (float)dgB) : 0.0f;
            aB.x *= inv; aB.y *= inv; aB.z *= inv; aB.w *= inv;
            store_a_pair(AH, AL, (uint32_t)rB * STRIDE_B + (uint32_t)lane * 8, aB);
        }
    }
}

template <int N>
__device__ __forceinline__ void load_B_async(const float* __restrict__ src,
                                             uint32_t BB, int tid) {
    constexpr int T4 = (2 * N * 136 * 2) / 16;
#pragma unroll
    for (int i = tid; i < T4; i += 256) {
        asm volatile("cp.async.cg.shared.global [%0], [%1], 16;"
                     :: "r"(BB + (uint32_t)i * 16), "l"(src + (size_t)i * 4)
                     : "memory");
    }
}
__device__ __forceinline__ void cp_commit() {
    asm volatile("cp.async.commit_group;" ::: "memory");
}
__device__ __forceinline__ void cp_wait_all() {
    asm volatile("cp.async.wait_group 0;" ::: "memory");
}

template <int N>
__device__ __forceinline__ void mainloop(uint32_t AH, uint32_t AL,
                                         uint32_t BH, uint32_t BL,
                                         float (*acc)[4],
                                         int a_row, int a_kof,
                                         int b_nof, int b_kof, int wcg) {
    constexpr int NOCT = N / 16;
#pragma unroll
    for (int k0 = 0; k0 < 128; k0 += 16) {
        uint32_t ah[4], al[4];
        uint32_t aoff = (uint32_t)a_row * STRIDE_B + (uint32_t)(k0 + a_kof) * 2;
        LDSM_X4(ah[0], ah[1], ah[2], ah[3], AH + aoff);
        LDSM_X4(al[0], al[1], al[2], al[3], AL + aoff);
#pragma unroll
        for (int op = 0; op < NOCT; op += 2) {
            int nbase = wcg * (N / 2) + op * 8;
            uint32_t boff = (uint32_t)(nbase + b_nof) * STRIDE_B
                          + (uint32_t)(k0 + b_kof) * 2;
            uint32_t bh0, bh1, bh2, bh3, bl0, bl1, bl2, bl3;
            LDSM_X4(bh0, bh1, bh2, bh3, BH + boff);
            LDSM_X4(bl0, bl1, bl2, bl3, BL + boff);
            mma_bf16(acc[op],     ah, bh0, bh1);
            mma_bf16(acc[op],     al, bh0, bh1);
            mma_bf16(acc[op],     ah, bl0, bl1);
            mma_bf16(acc[op + 1], ah, bh2, bh3);
            mma_bf16(acc[op + 1], al, bh2, bh3);
            mma_bf16(acc[op + 1], ah, bl2, bl3);
        }
    }
}

// ---------------------------------------------------------------------------
// count + fill
// ---------------------------------------------------------------------------
__global__ void count3_kernel(const int* __restrict__ d0,
                              const int* __restrict__ d1,
                              const int* __restrict__ d2,
                              int* __restrict__ cnt, int E) {
    int i = blockIdx.x * blockDim.x + threadIdx.x;
    if (i < E) atomicAdd(&cnt[d0[i]], 1);
    else if (i < 2 * E) atomicAdd(&cnt[N_ROBOT + d1[i - E]], 1);
    else if (i < 3 * E) atomicAdd(&cnt[2 * N_ROBOT + d2[i - 2 * E]], 1);
}

__global__ void fill3_csr_kernel(const int* __restrict__ s0, const int* __restrict__ d0,
                                 const int* __restrict__ s1, const int* __restrict__ d1,
                                 const int* __restrict__ s2, const int* __restrict__ d2,
                                 int* __restrict__ cursor,
                                 int* __restrict__ csr, int E) {
    int i = blockIdx.x * blockDim.x + threadIdx.x;
    int pos;
    if (i < E) {
        pos = atomicAdd(&cursor[d0[i]], 1);
        csr[pos] = s0[i];
    } else if (i < 2 * E) {
        pos = atomicAdd(&cursor[N_ROBOT + d1[i - E]], 1);
        csr[pos] = s1[i - E];
    } else if (i < 3 * E) {
        pos = atomicAdd(&cursor[2 * N_ROBOT + d2[i - 2 * E]], 1);
        csr[pos] = s2[i - 2 * E];
    }
}

// ---------------------------------------------------------------------------
// Single-pass decoupled-lookback scan + weight/bias prep, ONE launch.
// Blocks [0, SCAN_NB)          : scan of counts -> off/cursor
// Blocks [SCAN_NB, SCAN_NB+209): weight splits + bias folds
// ---------------------------------------------------------------------------
__device__ __forceinline__ void split_one512(const float* __restrict__ A,
                                             const float* __restrict__ B2,
                                             float* __restrict__ outf,
                                             int N, int e) {
    if (e >= 128 * N) return;
    int k = e / N;
    int n = e - k * N;
    float w = A[e];
    if (B2) w += B2[e];
    __nv_bfloat16 h = __float2bfloat16(w);
    __nv_bfloat16 l = __float2bfloat16(w - __bfloat162float(h));
    __nv_bfloat16* out = (__nv_bfloat16*)outf;
    out[n * 136 + k] = h;
    out[(size_t)N * 136 + n * 136 + k] = l;
}

__global__ void __launch_bounds__(512)
scanprep_kernel(const int* __restrict__ cnt,
                int* __restrict__ out, int* __restrict__ cursor,
                unsigned long long* __restrict__ state,
                const float* __restrict__ Wl0_rr, const float* __restrict__ Wl0_br,
                const float* __restrict__ Wr0_rr, const float* __restrict__ Wr0_br,
                const float* __restrict__ Wl0_rb, const float* __restrict__ Wr0_rb,
                const float* __restrict__ Wl1_rr, const float* __restrict__ Wr1_rr,
                const float* __restrict__ Wr1_br, const float* __restrict__ Wl1_br,
                const float* __restrict__ b0_rr, const float* __restrict__ b0_br,
                const float* __restrict__ b1_rr, const float* __restrict__ b1_br,
                float* __restrict__ WB0_rr, float* __restrict__ WB0_br,
                float* __restrict__ WBsum0, float* __restrict__ WB0_rb,
                float* __restrict__ WBr0_rb, float* __restrict__ WB1_rr,
                float* __restrict__ WBsum1, float* __restrict__ WB1_br,
                float* __restrict__ bsum0, float* __restrict__ bsum1) {
    int b = blockIdx.x;
    int t = threadIdx.x;
    if (b < SCAN_NB) {
        __shared__ int sh[SCAN_BS];
        __shared__ int s_excl;
        int gid = b * SCAN_BS + t;
        int v = (gid < NSCAN) ? cnt[gid] : 0;
        sh[t] = v;
        __syncthreads();
#pragma unroll
        for (int d = 1; d < SCAN_BS; d <<= 1) {
            int u = (t >= d) ? sh[t - d] : 0;
            __syncthreads();
            sh[t] += u;
            __syncthreads();
        }
        int incl = sh[t];
        if (t == 0) {
            unsigned long long total = (unsigned long long)sh[SCAN_BS - 1];
            if (b == 0) {
                atomicExch(&state[0], FLAG_P | total);
                s_excl = 0;
            } else {
                atomicExch(&state[b], FLAG_A | total);
                unsigned long long run = 0;
                int idx = b - 1;
                while (true) {
                    unsigned long long s = atomicAdd(&state[idx], 0ull);
                    if (s & FLAG_P) { run += (s & VALMASK); break; }
                    if (s & FLAG_A) { run += (s & VALMASK); idx--; }
                }
                atomicExch(&state[b], FLAG_P | (run + total));
                s_excl = (int)run;
            }
        }
        __syncthreads();
        if (gid < NSCAN) {
            int o = incl - v + s_excl;
            out[gid] = o;
            cursor[gid] = o;
        }
    } else {
        int pb = b - SCAN_NB;
        if (pb < 160) {                       // 5 x 32 blocks, N=128
            int seg = pb >> 5;
            int e = (pb & 31) * 512 + t;
            switch (seg) {
                case 0: split_one512(Wl0_rr, nullptr, WB0_rr, 128, e); break;
                case 1: split_one512(Wl0_br, nullptr, WB0_br, 128, e); break;
                case 2: split_one512(Wr0_rr, Wr0_br, WBsum0, 128, e); break;
                case 3: split_one512(Wl0_rb, nullptr, WB0_rb, 128, e); break;
                default: split_one512(Wr0_rb, nullptr, WBr0_rb, 128, e); break;
            }
        } else if (pb < 208) {                // 3 x 16 blocks, N=64
            int q = pb - 160;
            int seg = q >> 4;
            int e = (q & 15) * 512 + t;
            switch (seg) {
                case 0: split_one512(Wl1_rr, nullptr, WB1_rr, 64, e); break;
                case 1: split_one512(Wr1_rr, Wr1_br, WBsum1, 64, e); break;
                default: split_one512(Wl1_br, nullptr, WB1_br, 64, e); break;
            }
        } else {                              // bias folds
            if (t < 128) bsum0[t] = b0_rr[t] + b0_br[t];
            else if (t < 192) bsum1[t - 128] = b1_rr[t - 128] + b1_br[t - 128];
        }
    }
}

// ---------------------------------------------------------------------------
// Unified fused GEMM kernel (identical to round-11 best)
// ---------------------------------------------------------------------------
__global__ void __launch_bounds__(256, 2)
fused_kernel(const float* __restrict__ x_robot,
             const float* __restrict__ x_ball,
             const int* __restrict__ off, const int* __restrict__ cnt,
             const int* __restrict__ csr,
             const float* __restrict__ WB0_rr,
             const float* __restrict__ WB0_br,
             const float* __restrict__ WBsum0,
             const float* __restrict__ bsum0,
             const float* __restrict__ WB1_rr,
             const float* __restrict__ WBsum1,
             const float* __restrict__ WB0_rb,
             const float* __restrict__ WBr0_rb,
             const float* __restrict__ b0_rb,
             const float* __restrict__ WB1_br,
             float* __restrict__ t_rr,
             float* __restrict__ f_r,
             float* __restrict__ t_br) {
    extern __shared__ char smem[];
    const uint32_t AH = smem_u32(smem);
    const uint32_t AL = AH + A_BYTES;
    const uint32_t BB = AL + A_BYTES;

    const int tid  = threadIdx.x;
    const int wid  = tid >> 5;
    const int lane = tid & 31;
    const int wr   = wid & 3;
    const int wcg  = wid >> 2;

    const int a_row = wr * 16 + ((lane >> 3) & 1) * 8 + (lane & 7);
    const int a_kof = (lane >> 4) * 8;
    const int b_nof = ((lane >> 4) & 1) * 8 + (lane & 7);
    const int b_kof = ((lane >> 3) & 1) * 8;

    float acc[8][4];
#pragma unroll
    for (int o = 0; o < 8; o++)
#pragma unroll
        for (int j = 0; j < 4; j++) acc[o][j] = 0.0f;

    const bool robot = (blockIdx.x < GB_ROBOT);

    if (robot) {
        const int row0 = blockIdx.x * 64;
        const int M    = N_ROBOT;

        load_B_async<128>(WB0_rr, BB, tid);
        cp_commit();
        load_A_gather(x_robot, off, cnt, csr, row0, M, AH, AL, wid, lane);
        cp_wait_all();
        __syncthreads();
        mainloop<128>(AH, AL, BB, BB + 34816, acc, a_row, a_kof, b_nof, b_kof, wcg);
        __syncthreads();
        load_B_async<128>(WB0_br, BB, tid);
        cp_commit();
        load_A_gather(x_ball, off + N_ROBOT, cnt + N_ROBOT, csr, row0, M, AH, AL, wid, lane);
        cp_wait_all();
        __syncthreads();
        mainloop<128>(AH, AL, BB, BB + 34816, acc, a_row, a_kof, b_nof, b_kof, wcg);
        __syncthreads();
        load_B_async<128>(WBsum0, BB, tid);
        cp_commit();
        load_A_direct(x_robot, row0, M, AH, AL, tid);
        cp_wait_all();
        __syncthreads();
        mainloop<128>(AH, AL, BB, BB + 34816, acc, a_row, a_kof, b_nof, b_kof, wcg);
        __syncthreads();

        load_B_async<64>(WB1_rr, BB, tid);
        load_B_async<64>(WBsum1, BB + 2 * 17408, tid);
        cp_commit();

        {
            const int rAl = wr * 16 + (lane >> 2);
            const int rBl = rAl + 8;
#pragma unroll
            for (int o = 0; o < 8; o++) {
                int col = wcg * 64 + o * 8 + (lane & 3) * 2;
                float2 bv = *(const float2*)(bsum0 + col);
                float v0 = fmaxf(acc[o][0] + bv.x, 0.f);
                float v1 = fmaxf(acc[o][1] + bv.y, 0.f);
                float v2 = fmaxf(acc[o][2] + bv.x, 0.f);
                float v3 = fmaxf(acc[o][3] + bv.y, 0.f);
                uint32_t h, l;
                uint32_t offA = (uint32_t)rAl * STRIDE_B + (uint32_t)col * 2;
                split_pack(v0, v1, h, l);
                asm volatile("st.shared.b32 [%0], %1;" :: "r"(AH + offA), "r"(h) : "memory");
                asm volatile("st.shared.b32 [%0], %1;" :: "r"(AL + offA), "r"(l) : "memory");
                uint32_t offB = (uint32_t)rBl * STRIDE_B + (uint32_t)col * 2;
                split_pack(v2, v3, h, l);
                asm volatile("st.shared.b32 [%0], %1;" :: "r"(AH + offB), "r"(h) : "memory");
                asm volatile("st.shared.b32 [%0], %1;" :: "r"(AL + offB), "r"(l) : "memory");
            }
        }
        cp_wait_all();
        __syncthreads();

        float acc2a[4][4], acc2b[4][4];
#pragma unroll
        for (int o = 0; o < 4; o++)
#pragma unroll
            for (int j = 0; j < 4; j++) { acc2a[o][j] = 0.f; acc2b[o][j] = 0.f; }

        mainloop<64>(AH, AL, BB,             BB + 17408,     acc2a,
                     a_row, a_kof, b_nof, b_kof, wcg);
        mainloop<64>(AH, AL, BB + 2 * 17408, BB + 3 * 17408, acc2b,
                     a_row, a_kof, b_nof, b_kof, wcg);

        const int rA = row0 + wr * 16 + (lane >> 2);
        const int rB = rA + 8;
#pragma unroll
        for (int o = 0; o < 4; o++) {
            int col = wcg * 32 + o * 8 + (lane & 3) * 2;
            if (rA < M) {
                *(float2*)(t_rr + (size_t)rA * 64 + col) = make_float2(acc2a[o][0], acc2a[o][1]);
                *(float2*)(f_r  + (size_t)rA * 64 + col) = make_float2(acc2b[o][0], acc2b[o][1]);
            }
            if (rB < M) {
                *(float2*)(t_rr + (size_t)rB * 64 + col) = make_float2(acc2a[o][2], acc2a[o][3]);
                *(float2*)(f_r  + (size_t)rB * 64 + col) = make_float2(acc2b[o][2], acc2b[o][3]);
            }
        }
    } else {
        const int row0 = (blockIdx.x - GB_ROBOT) * 64;
        const int M    = N_BALL;

        load_B_async<128>(WB0_rb, BB, tid);
        cp_commit();
        load_A_gather(x_robot, off + 2 * N_ROBOT, cnt + 2 * N_ROBOT, csr,
                      row0, M, AH, AL, wid, lane);
        cp_wait_all();
        __syncthreads();
        mainloop<128>(AH, AL, BB, BB + 34816, acc, a_row, a_kof, b_nof, b_kof, wcg);
        __syncthreads();
        load_B_async<128>(WBr0_rb, BB, tid);
        cp_commit();
        load_A_direct(x_ball, row0, M, AH, AL, tid);
        cp_wait_all();
        __syncthreads();
        mainloop<128>(AH, AL, BB, BB + 34816, acc, a_row, a_kof, b_nof, b_kof, wcg);
        __syncthreads();

        load_B_async<64>(WB1_br, BB, tid);
        cp_commit();
        {
            const int rAl = wr * 16 + (lane >> 2);
            const int rBl = rAl + 8;
#pragma unroll
            for (int o = 0; o < 8; o++) {
                int col = wcg * 64 + o * 8 + (lane & 3) * 2;
                float2 bv = *(const float2*)(b0_rb + col);
                float v0 = fmaxf(acc[o][0] + bv.x, 0.f);
                float v1 = fmaxf(acc[o][1] + bv.y, 0.f);
                float v2 = fmaxf(acc[o][2] + bv.x, 0.f);
                float v3 = fmaxf(acc[o][3] + bv.y, 0.f);
                uint32_t h, l;
                uint32_t offA = (uint32_t)rAl * STRIDE_B + (uint32_t)col * 2;
                split_pack(v0, v1, h, l);
                asm volatile("st.shared.b32 [%0], %1;" :: "r"(AH + offA), "r"(h) : "memory");
                asm volatile("st.shared.b32 [%0], %1;" :: "r"(AL + offA), "r"(l) : "memory");
                uint32_t offB = (uint32_t)rBl * STRIDE_B + (uint32_t)col * 2;
                split_pack(v2, v3, h, l);
                asm volatile("st.shared.b32 [%0], %1;" :: "r"(AH + offB), "r"(h) : "memory");
                asm volatile("st.shared.b32 [%0], %1;" :: "r"(AL + offB), "r"(l) : "memory");
            }
        }
        cp_wait_all();
        __syncthreads();

        float acc2[4][4];
#pragma unroll
        for (int o = 0; o < 4; o++)
#pragma unroll
            for (int j = 0; j < 4; j++) acc2[o][j] = 0.f;

        mainloop<64>(AH, AL, BB, BB + 17408, acc2, a_row, a_kof, b_nof, b_kof, wcg);

        const int rA = row0 + wr * 16 + (lane >> 2);
        const int rB = rA + 8;
#pragma unroll
        for (int o = 0; o < 4; o++) {
            int col = wcg * 32 + o * 8 + (lane & 3) * 2;
            if (rA < M)
                *(float2*)(t_br + (size_t)rA * 64 + col) = make_float2(acc2[o][0], acc2[o][1]);
            if (rB < M)
                *(float2*)(t_br + (size_t)rB * 64 + col) = make_float2(acc2[o][2], acc2[o][3]);
        }
    }
}

// ---------------------------------------------------------------------------
// Final: out[d] = mean_rr(t_rr) + mean_br(t_br) + f_r[d] + bsum1
// ---------------------------------------------------------------------------
__device__ __forceinline__ float2 row_load64(const float* __restrict__ t,
                                             int s, int lane) {
    return *(const float2*)(t + (size_t)s * 64 + lane * 2);
}

__device__ __forceinline__ void tail64(const float* __restrict__ t,
                                       const int* __restrict__ csr,
                                       int st, int& j, int dg,
                                       int lane, float2& a) {
    for (; j + 4 <= dg; j += 4) {
        int s0 = csr[st + j], s1 = csr[st + j + 1];
        int s2 = csr[st + j + 2], s3 = csr[st + j + 3];
        float2 v0 = row_load64(t, s0, lane);
        float2 v1 = row_load64(t, s1, lane);
        float2 v2 = row_load64(t, s2, lane);
        float2 v3 = row_load64(t, s3, lane);
        a.x += (v0.x + v1.x) + (v2.x + v3.x);
        a.y += (v0.y + v1.y) + (v2.y + v3.y);
    }
    if (j + 2 <= dg) {
        int s0 = csr[st + j], s1 = csr[st + j + 1];
        float2 v0 = row_load64(t, s0, lane);
        float2 v1 = row_load64(t, s1, lane);
        a.x += v0.x + v1.x; a.y += v0.y + v1.y;
        j += 2;
    }
    if (j < dg) {
        float2 v = row_load64(t, csr[st + j], lane);
        a.x += v.x; a.y += v.y;
    }
}

__global__ void __launch_bounds__(256)
final_kernel(const int* __restrict__ off_rr, const int* __restrict__ cnt_rr,
             const int* __restrict__ off_br, const int* __restrict__ cnt_br,
             const int* __restrict__ csr,
             const float* __restrict__ t_rr, const float* __restrict__ t_br,
             const float* __restrict__ f_r, const float* __restrict__ bsum1,
             float* __restrict__ out) {
    int warp = (blockIdx.x * blockDim.x + threadIdx.x) >> 5;
    int lane = threadIdx.x & 31;
    if (warp >= N_ROBOT) return;

    float2 res = *(const float2*)(f_r + (size_t)warp * 64 + lane * 2);
    float2 bv  = *(const float2*)(bsum1 + lane * 2);
    res.x += bv.x; res.y += bv.y;

    int st0 = off_rr[warp], dg0 = cnt_rr[warp];
    int st1 = off_br[warp], dg1 = cnt_br[warp];
    float2 a0 = make_float2(0.f, 0.f);
    float2 a1 = make_float2(0.f, 0.f);
    int j0 = 0, j1 = 0;
    while (j0 + 4 <= dg0 && j1 + 4 <= dg1) {
        int r0 = csr[st0 + j0],     r1 = csr[st0 + j0 + 1];
        int r2 = csr[st0 + j0 + 2], r3 = csr[st0 + j0 + 3];
        int b0 = csr[st1 + j1],     b1 = csr[st1 + j1 + 1];
        int b2 = csr[st1 + j1 + 2], b3 = csr[st1 + j1 + 3];
        float2 u0 = row_load64(t_rr, r0, lane);
        float2 u1 = row_load64(t_rr, r1, lane);
        float2 u2 = row_load64(t_rr, r2, lane);
        float2 u3 = row_load64(t_rr, r3, lane);
        float2 w0 = row_load64(t_br, b0, lane);
        float2 w1 = row_load64(t_br, b1, lane);
        float2 w2 = row_load64(t_br, b2, lane);
        float2 w3 = row_load64(t_br, b3, lane);
        a0.x += (u0.x + u1.x) + (u2.x + u3.x);
        a0.y += (u0.y + u1.y) + (u2.y + u3.y);
        a1.x += (w0.x + w1.x) + (w2.x + w3.x);
        a1.y += (w0.y + w1.y) + (w2.y + w3.y);
        j0 += 4; j1 += 4;
    }
    tail64(t_rr, csr, st0, j0, dg0, lane, a0);
    tail64(t_br, csr, st1, j1, dg1, lane, a1);

    float inv0 = (dg0 > 0) ? (1.0f / (float)dg0) : 0.0f;
    float inv1 = (dg1 > 0) ? (1.0f / (float)dg1) : 0.0f;
    res.x += a0.x * inv0 + a1.x * inv1;
    res.y += a0.y * inv0 + a1.y * inv1;

    *(float2*)(out + (size_t)warp * 64 + lane * 2) = res;
}

// ---------------------------------------------------------------------------
// Launch: memset(0) count3(1) scanprep(2) fill3(3) fused(4) final(5)
// -> profiler (launch idx 4) captures fused_kernel next round.
// ---------------------------------------------------------------------------
extern "C" void kernel_launch(void* const* d_in, const int* in_sizes, int n_in,
                              void* d_out, int out_size) {
    (void)n_in; (void)out_size;

    const float* x_robot = (const float*)d_in[0];
    const float* x_ball  = (const float*)d_in[1];
    const int* ei_rr = (const int*)d_in[2];
    const int* ei_rb = (const int*)d_in[3];
    const int* ei_br = (const int*)d_in[4];
    const float* Wl0_rr = (const float*)d_in[5];
    const float* Wr0_rr = (const float*)d_in[6];
    const float* b0_rr  = (const float*)d_in[7];
    const float* Wl0_rb = (const float*)d_in[8];
    const float* Wr0_rb = (const float*)d_in[9];
    const float* b0_rb  = (const float*)d_in[10];
    const float* Wl0_br = (const float*)d_in[11];
    const float* Wr0_br = (const float*)d_in[12];
    const float* b0_br  = (const float*)d_in[13];
    const float* Wl1_rr = (const float*)d_in[14];
    const float* Wr1_rr = (const float*)d_in[15];
    const float* b1_rr  = (const float*)d_in[16];
    const float* Wl1_br = (const float*)d_in[20];
    const float* Wr1_br = (const float*)d_in[21];
    const float* b1_br  = (const float*)d_in[22];

    float* out = (float*)d_out;
    const int E = in_sizes[2] / 2;

    float* S = nullptr;
    int *C = nullptr, *OFF = nullptr, *CUR = nullptr, *CSR = nullptr;
    {
        void* p = nullptr;
        cudaGetSymbolAddress(&p, g_scratch); S = (float*)p;
        cudaGetSymbolAddress(&p, g_cnt);     C = (int*)p;
        cudaGetSymbolAddress(&p, g_off);     OFF = (int*)p;
        cudaGetSymbolAddress(&p, g_cursor);  CUR = (int*)p;
        cudaGetSymbolAddress(&p, g_csr);     CSR = (int*)p;
    }
    unsigned long long* STATE = (unsigned long long*)(C + 3 * N_ROBOT);

    float* t_rr    = S + O_TRR;
    float* t_br    = S + O_TBR;
    float* f_r     = S + O_FR;
    float* bsum0   = S + O_BSUM0;
    float* bsum1   = S + O_BSUM1;
    float* WB0_rr  = S + O_WB0_RR;
    float* WB0_br  = S + O_WB0_BR;
    float* WBsum0  = S + O_WBSUM0;
    float* WB0_rb  = S + O_WB0_RB;
    float* WBr0_rb = S + O_WBR0_RB;
    float* WB1_rr  = S + O_WB1_RR;
    float* WBsum1  = S + O_WBSUM1;
    float* WB1_br  = S + O_WB1_BR;

    cudaFuncSetAttribute(fused_kernel,
                         cudaFuncAttributeMaxDynamicSharedMemorySize, SMEM_TOTAL);

    // idx 0: zero counts + lookback state in one memset
    cudaMemsetAsync(C, 0, (3ull * N_ROBOT + 2048ull) * sizeof(int), 0);

    // idx 1: counts
    const int cb3 = (3 * E + 255) / 256;
    count3_kernel<<<cb3, 256>>>(ei_rr + E, ei_br + E, ei_rb + E, C, E);

    // idx 2: single-pass scan (decoupled lookback) + weight/bias prep
    scanprep_kernel<<<SCAN_NB + PREP_NB, 512>>>(
        C, OFF, CUR, STATE,
        Wl0_rr, Wl0_br, Wr0_rr, Wr0_br, Wl0_rb, Wr0_rb,
        Wl1_rr, Wr1_rr, Wr1_br, Wl1_br,
        b0_rr, b0_br, b1_rr, b1_br,
        WB0_rr, WB0_br, WBsum0, WB0_rb, WBr0_rb,
        WB1_rr, WBsum1, WB1_br, bsum0, bsum1);

    // idx 3: CSR fill
    fill3_csr_kernel<<<cb3, 256>>>(ei_rr, ei_rr + E, ei_br, ei_br + E,
                                   ei_rb, ei_rb + E, CUR, CSR, E);

    // idx 4: fused compute (profiled next round)
    fused_kernel<<<GB_ROBOT + GB_BALL, 256, SMEM_TOTAL>>>(
        x_robot, x_ball, OFF, C, CSR,
        WB0_rr, WB0_br, WBsum0, bsum0, WB1_rr, WBsum1,
        WB0_rb, WBr0_rb, b0_rb, WB1_br,
        t_rr, f_r, t_br);

    // idx 5: final combine
    const int fb = (N_ROBOT * 32 + 255) / 256;
    final_kernel<<<fb, 256>>>(OFF, C, OFF + N_ROBOT, C + N_ROBOT, CSR,
                              t_rr, t_br, f_r, bsum1, out);
}

// round 15
// speedup vs baseline: 1.1213x; 1.0857x over previous
#include <cuda_runtime.h>
#include <cuda_bf16.h>
#include <stdint.h>

// ---------------------------------------------------------------------------
// Problem constants
// ---------------------------------------------------------------------------
#define N_ROBOT 100000
#define N_BALL  100000
#define E_MAX   600000
#define GB_ROBOT ((N_ROBOT + 63) / 64)   // 1563
#define GB_BALL  ((N_BALL + 63) / 64)    // 1563

// ---------------------------------------------------------------------------
// Scratch (device globals; allocation is forbidden)
// ---------------------------------------------------------------------------
#define O_TRR     0ull
#define O_TBR     (O_TRR + 6400000ull)
#define O_FR      (O_TBR + 6400000ull)
#define O_BSUM0   (O_FR  + 6400000ull)
#define O_BSUM1   (O_BSUM0 + 128ull)
#define O_WB0_RR  (O_BSUM1 + 64ull)
#define O_WB0_BR  (O_WB0_RR + 17408ull)
#define O_WBSUM0  (O_WB0_BR + 17408ull)
#define O_WB0_RB  (O_WBSUM0 + 17408ull)
#define O_WBR0_RB (O_WB0_RB + 17408ull)
#define O_WB1_RR  (O_WBR0_RB + 17408ull)
#define O_WBSUM1  (O_WB1_RR + 8704ull)
#define O_WB1_BR  (O_WBSUM1 + 8704ull)
#define SCRATCH_FLOATS (O_WB1_BR + 8704ull)

__device__ float g_scratch[SCRATCH_FLOATS];
__device__ int   g_cnt[3 * N_ROBOT + 2048];   // counts + lookback state
__device__ int   g_off[3 * N_ROBOT];
__device__ int   g_cursor[3 * N_ROBOT];
__device__ int   g_csr[3 * E_MAX + 64];

#define NSCAN   (3 * N_ROBOT)
#define SCAN_BS 512
#define SCAN_NB ((NSCAN + SCAN_BS - 1) / SCAN_BS)   // 586
#define PREP_NB 209
#define FLAG_A  (1ull << 62)
#define FLAG_P  (1ull << 63)
#define VALMASK 0xFFFFFFFFull

// ---------------------------------------------------------------------------
// Helpers (baseline PTX only)
// ---------------------------------------------------------------------------
__device__ __forceinline__ uint32_t smem_u32(const void* p) {
    uint32_t a;
    asm("{ .reg .u64 t; cvta.to.shared.u64 t, %1; cvt.u32.u64 %0, t; }"
        : "=r"(a) : "l"(p));
    return a;
}

#define LDSM_X4(r0, r1, r2, r3, addr) \
    asm volatile("ldmatrix.sync.aligned.m8n8.x4.shared.b16 {%0,%1,%2,%3}, [%4];" \
                 : "=r"(r0), "=r"(r1), "=r"(r2), "=r"(r3) : "r"(addr))

__device__ __forceinline__ void mma_bf16(float* c, const uint32_t* a,
                                         uint32_t b0, uint32_t b1) {
    asm volatile(
        "mma.sync.aligned.m16n8k16.row.col.f32.bf16.bf16.f32 "
        "{%0,%1,%2,%3}, {%4,%5,%6,%7}, {%8,%9}, {%0,%1,%2,%3};"
        : "+f"(c[0]), "+f"(c[1]), "+f"(c[2]), "+f"(c[3])
        : "r"(a[0]), "r"(a[1]), "r"(a[2]), "r"(a[3]), "r"(b0), "r"(b1));
}

__device__ __forceinline__ void split_pack(float x0, float x1,
                                           uint32_t& hp, uint32_t& lp) {
    __nv_bfloat16 h0 = __float2bfloat16(x0);
    __nv_bfloat16 h1 = __float2bfloat16(x1);
    __nv_bfloat16 l0 = __float2bfloat16(x0 - __bfloat162float(h0));
    __nv_bfloat16 l1 = __float2bfloat16(x1 - __bfloat162float(h1));
    hp = ((uint32_t)__bfloat16_as_ushort(h1) << 16) | __bfloat16_as_ushort(h0);
    lp = ((uint32_t)__bfloat16_as_ushort(l1) << 16) | __bfloat16_as_ushort(l0);
}

#define STRIDE_B 272u
#define A_BYTES  17408u
// A hi | A lo | single B plane area (34816) => 69632 -> 3 CTAs/SM
#define SMEM_TOTAL (2 * 17408 + 34816)

// ---------------------------------------------------------------------------
// Stage loaders + mainloops
// ---------------------------------------------------------------------------
__device__ __forceinline__ void store_a_pair(uint32_t AH, uint32_t AL,
                                             uint32_t off, const float4& v) {
    uint32_t h01, l01, h23, l23;
    split_pack(v.x, v.y, h01, l01);
    split_pack(v.z, v.w, h23, l23);
    asm volatile("st.shared.v2.b32 [%0], {%1,%2};"
                 :: "r"(AH + off), "r"(h01), "r"(h23) : "memory");
    asm volatile("st.shared.v2.b32 [%0], {%1,%2};"
                 :: "r"(AL + off), "r"(l01), "r"(l23) : "memory");
}

__device__ __forceinline__ void load_A_direct(const float* __restrict__ A,
                                              int row0, int M,
                                              uint32_t AH, uint32_t AL, int tid) {
#pragma unroll
    for (int i = 0; i < 8; i++) {
        int idx = tid + i * 256;
        int r  = idx >> 5;
        int c4 = idx & 31;
        float4 v = make_float4(0.f, 0.f, 0.f, 0.f);
        if (row0 + r < M)
            v = *(const float4*)(A + (size_t)(row0 + r) * 128 + c4 * 4);
        store_a_pair(AH, AL, (uint32_t)r * STRIDE_B + (uint32_t)c4 * 8, v);
    }
}

__device__ __forceinline__ float4 row_load128(const float* __restrict__ x,
                                              int s, int lane) {
    return *(const float4*)(x + (size_t)s * 128 + lane * 4);
}

// CSR mean-gather, serial rows, 4-wide unroll (register-lean form).
__device__ __forceinline__ void load_A_gather(const float* __restrict__ x,
                                              const int* __restrict__ off,
                                              const int* __restrict__ cnt,
                                              const int* __restrict__ csr,
                                              int row0, int M,
                                              uint32_t AH, uint32_t AL,
                                              int wid, int lane) {
#pragma unroll
    for (int i = 0; i < 8; i++) {
        int r  = wid + i * 8;
        int gr = row0 + r;
        float4 a = make_float4(0.f, 0.f, 0.f, 0.f);
        if (gr < M) {
            int st = off[gr];
            int dg = cnt[gr];
            int j = 0;
            for (; j + 4 <= dg; j += 4) {
                int s0 = csr[st + j];
                int s1 = csr[st + j + 1];
                int s2 = csr[st + j + 2];
                int s3 = csr[st + j + 3];
                float4 v0 = row_load128(x, s0, lane);
                float4 v1 = row_load128(x, s1, lane);
                float4 v2 = row_load128(x, s2, lane);
                float4 v3 = row_load128(x, s3, lane);
                a.x += (v0.x + v1.x) + (v2.x + v3.x);
                a.y += (v0.y + v1.y) + (v2.y + v3.y);
                a.z += (v0.z + v1.z) + (v2.z + v3.z);
                a.w += (v0.w + v1.w) + (v2.w + v3.w);
            }
            if (j + 2 <= dg) {
                int s0 = csr[st + j];
                int s1 = csr[st + j + 1];
                float4 v0 = row_load128(x, s0, lane);
                float4 v1 = row_load128(x, s1, lane);
                a.x += v0.x + v1.x; a.y += v0.y + v1.y;
                a.z += v0.z + v1.z; a.w += v0.w + v1.w;
                j += 2;
            }
            if (j < dg) {
                float4 v = row_load128(x, csr[st + j], lane);
                a.x += v.x; a.y += v.y; a.z += v.z; a.w += v.w;
            }
            float inv = (dg > 0) ? (1.0f / (float)dg) : 0.0f;
            a.x *= inv; a.y *= inv; a.z *= inv; a.w *= inv;
        }
        store_a_pair(AH, AL, (uint32_t)r * STRIDE_B + (uint32_t)lane * 8, a);
    }
}

// Copy 34816 bytes (one N=128 plane, or a full N=64 hi+lo tile) via cp.async.
__device__ __forceinline__ void load_B34k_async(const float* __restrict__ src,
                                                uint32_t BB, int tid) {
    for (int i = tid; i < 2176; i += 256) {
        asm volatile("cp.async.cg.shared.global [%0], [%1], 16;"
                     :: "r"(BB + (uint32_t)i * 16), "l"(src + (size_t)i * 4)
                     : "memory");
    }
}
__device__ __forceinline__ void cp_commit() {
    asm volatile("cp.async.commit_group;" ::: "memory");
}
__device__ __forceinline__ void cp_wait_all() {
    asm volatile("cp.async.wait_group 0;" ::: "memory");
}

// Single-plane N=128 mainloop. MODE 0 (hi plane): acc += ah*b + al*b.
// MODE 1 (lo plane): acc += ah*b.
template <int MODE>
__device__ __forceinline__ void mainloop128_p(uint32_t AH, uint32_t AL, uint32_t BP,
                                              float (*acc)[4],
                                              int a_row, int a_kof,
                                              int b_nof, int b_kof, int wcg) {
#pragma unroll
    for (int k0 = 0; k0 < 128; k0 += 16) {
        uint32_t ah[4], al[4];
        uint32_t aoff = (uint32_t)a_row * STRIDE_B + (uint32_t)(k0 + a_kof) * 2;
        LDSM_X4(ah[0], ah[1], ah[2], ah[3], AH + aoff);
        if (MODE == 0) LDSM_X4(al[0], al[1], al[2], al[3], AL + aoff);
#pragma unroll
        for (int op = 0; op < 8; op += 2) {
            int nbase = wcg * 64 + op * 8;
            uint32_t boff = (uint32_t)(nbase + b_nof) * STRIDE_B
                          + (uint32_t)(k0 + b_kof) * 2;
            uint32_t b0, b1, b2, b3;
            LDSM_X4(b0, b1, b2, b3, BP + boff);
            mma_bf16(acc[op], ah, b0, b1);
            if (MODE == 0) mma_bf16(acc[op], al, b0, b1);
            mma_bf16(acc[op + 1], ah, b2, b3);
            if (MODE == 0) mma_bf16(acc[op + 1], al, b2, b3);
        }
    }
}

// Full N=64 mainloop (hi+lo both resident in the 34816 area).
__device__ __forceinline__ void mainloop64(uint32_t AH, uint32_t AL,
                                           uint32_t BH, uint32_t BL,
                                           float (*acc)[4],
                                           int a_row, int a_kof,
                                           int b_nof, int b_kof, int wcg) {
#pragma unroll
    for (int k0 = 0; k0 < 128; k0 += 16) {
        uint32_t ah[4], al[4];
        uint32_t aoff = (uint32_t)a_row * STRIDE_B + (uint32_t)(k0 + a_kof) * 2;
        LDSM_X4(ah[0], ah[1], ah[2], ah[3], AH + aoff);
        LDSM_X4(al[0], al[1], al[2], al[3], AL + aoff);
#pragma unroll
        for (int op = 0; op < 4; op += 2) {
            int nbase = wcg * 32 + op * 8;
            uint32_t boff = (uint32_t)(nbase + b_nof) * STRIDE_B
                          + (uint32_t)(k0 + b_kof) * 2;
            uint32_t bh0, bh1, bh2, bh3, bl0, bl1, bl2, bl3;
            LDSM_X4(bh0, bh1, bh2, bh3, BH + boff);
            LDSM_X4(bl0, bl1, bl2, bl3, BL + boff);
            mma_bf16(acc[op],     ah, bh0, bh1);
            mma_bf16(acc[op],     al, bh0, bh1);
            mma_bf16(acc[op],     ah, bl0, bl1);
            mma_bf16(acc[op + 1], ah, bh2, bh3);
            mma_bf16(acc[op + 1], al, bh2, bh3);
            mma_bf16(acc[op + 1], ah, bl2, bl3);
        }
    }
}

// ---------------------------------------------------------------------------
// count + fill
// ---------------------------------------------------------------------------
__global__ void count3_kernel(const int* __restrict__ d0,
                              const int* __restrict__ d1,
                              const int* __restrict__ d2,
                              int* __restrict__ cnt, int E) {
    int i = blockIdx.x * blockDim.x + threadIdx.x;
    if (i < E) atomicAdd(&cnt[d0[i]], 1);
    else if (i < 2 * E) atomicAdd(&cnt[N_ROBOT + d1[i - E]], 1);
    else if (i < 3 * E) atomicAdd(&cnt[2 * N_ROBOT + d2[i - 2 * E]], 1);
}

__global__ void fill3_csr_kernel(const int* __restrict__ s0, const int* __restrict__ d0,
                                 const int* __restrict__ s1, const int* __restrict__ d1,
                                 const int* __restrict__ s2, const int* __restrict__ d2,
                                 int* __restrict__ cursor,
                                 int* __restrict__ csr, int E) {
    int i = blockIdx.x * blockDim.x + threadIdx.x;
    int pos;
    if (i < E) {
        pos = atomicAdd(&cursor[d0[i]], 1);
        csr[pos] = s0[i];
    } else if (i < 2 * E) {
        pos = atomicAdd(&cursor[N_ROBOT + d1[i - E]], 1);
        csr[pos] = s1[i - E];
    } else if (i < 3 * E) {
        pos = atomicAdd(&cursor[2 * N_ROBOT + d2[i - 2 * E]], 1);
        csr[pos] = s2[i - 2 * E];
    }
}

// ---------------------------------------------------------------------------
// Single-pass decoupled-lookback scan + weight/bias prep, ONE launch.
// ---------------------------------------------------------------------------
__device__ __forceinline__ void split_one512(const float* __restrict__ A,
                                             const float* __restrict__ B2,
                                             float* __restrict__ outf,
                                             int N, int e) {
    if (e >= 128 * N) return;
    int k = e / N;
    int n = e - k * N;
    float w = A[e];
    if (B2) w += B2[e];
    __nv_bfloat16 h = __float2bfloat16(w);
    __nv_bfloat16 l = __float2bfloat16(w - __bfloat162float(h));
    __nv_bfloat16* out = (__nv_bfloat16*)outf;
    out[n * 136 + k] = h;
    out[(size_t)N * 136 + n * 136 + k] = l;
}

__global__ void __launch_bounds__(512)
scanprep_kernel(const int* __restrict__ cnt,
                int* __restrict__ out, int* __restrict__ cursor,
                unsigned long long* __restrict__ state,
                const float* __restrict__ Wl0_rr, const float* __restrict__ Wl0_br,
                const float* __restrict__ Wr0_rr, const float* __restrict__ Wr0_br,
                const float* __restrict__ Wl0_rb, const float* __restrict__ Wr0_rb,
                const float* __restrict__ Wl1_rr, const float* __restrict__ Wr1_rr,
                const float* __restrict__ Wr1_br, const float* __restrict__ Wl1_br,
                const float* __restrict__ b0_rr, const float* __restrict__ b0_br,
                const float* __restrict__ b1_rr, const float* __restrict__ b1_br,
                float* __restrict__ WB0_rr, float* __restrict__ WB0_br,
                float* __restrict__ WBsum0, float* __restrict__ WB0_rb,
                float* __restrict__ WBr0_rb, float* __restrict__ WB1_rr,
                float* __restrict__ WBsum1, float* __restrict__ WB1_br,
                float* __restrict__ bsum0, float* __restrict__ bsum1) {
    int b = blockIdx.x;
    int t = threadIdx.x;
    if (b < SCAN_NB) {
        __shared__ int sh[SCAN_BS];
        __shared__ int s_excl;
        int gid = b * SCAN_BS + t;
        int v = (gid < NSCAN) ? cnt[gid] : 0;
        sh[t] = v;
        __syncthreads();
#pragma unroll
        for (int d = 1; d < SCAN_BS; d <<= 1) {
            int u = (t >= d) ? sh[t - d] : 0;
            __syncthreads();
            sh[t] += u;
            __syncthreads();
        }
        int incl = sh[t];
        if (t == 0) {
            unsigned long long total = (unsigned long long)sh[SCAN_BS - 1];
            if (b == 0) {
                atomicExch(&state[0], FLAG_P | total);
                s_excl = 0;
            } else {
                atomicExch(&state[b], FLAG_A | total);
                unsigned long long run = 0;
                int idx = b - 1;
                while (true) {
                    unsigned long long s = atomicAdd(&state[idx], 0ull);
                    if (s & FLAG_P) { run += (s & VALMASK); break; }
                    if (s & FLAG_A) { run += (s & VALMASK); idx--; }
                }
                atomicExch(&state[b], FLAG_P | (run + total));
                s_excl = (int)run;
            }
        }
        __syncthreads();
        if (gid < NSCAN) {
            int o = incl - v + s_excl;
            out[gid] = o;
            cursor[gid] = o;
        }
    } else {
        int pb = b - SCAN_NB;
        if (pb < 160) {
            int seg = pb >> 5;
            int e = (pb & 31) * 512 + t;
            switch (seg) {
                case 0: split_one512(Wl0_rr, nullptr, WB0_rr, 128, e); break;
                case 1: split_one512(Wl0_br, nullptr, WB0_br, 128, e); break;
                case 2: split_one512(Wr0_rr, Wr0_br, WBsum0, 128, e); break;
                case 3: split_one512(Wl0_rb, nullptr, WB0_rb, 128, e); break;
                default: split_one512(Wr0_rb, nullptr, WBr0_rb, 128, e); break;
            }
        } else if (pb < 208) {
            int q = pb - 160;
            int seg = q >> 4;
            int e = (q & 15) * 512 + t;
            switch (seg) {
                case 0: split_one512(Wl1_rr, nullptr, WB1_rr, 64, e); break;
                case 1: split_one512(Wr1_rr, Wr1_br, WBsum1, 64, e); break;
                default: split_one512(Wl1_br, nullptr, WB1_br, 64, e); break;
            }
        } else {
            if (t < 128) bsum0[t] = b0_rr[t] + b0_br[t];
            else if (t < 192) bsum1[t - 128] = b1_rr[t - 128] + b1_br[t - 128];
        }
    }
}

// ---------------------------------------------------------------------------
// Unified fused GEMM kernel — 3 CTAs/SM (smem 69632, regs capped by bounds)
// ---------------------------------------------------------------------------
__global__ void __launch_bounds__(256, 3)
fused_kernel(const float* __restrict__ x_robot,
             const float* __restrict__ x_ball,
             const int* __restrict__ off, const int* __restrict__ cnt,
             const int* __restrict__ csr,
             const float* __restrict__ WB0_rr,
             const float* __restrict__ WB0_br,
             const float* __restrict__ WBsum0,
             const float* __restrict__ bsum0,
             const float* __restrict__ WB1_rr,
             const float* __restrict__ WBsum1,
             const float* __restrict__ WB0_rb,
             const float* __restrict__ WBr0_rb,
             const float* __restrict__ b0_rb,
             const float* __restrict__ WB1_br,
             float* __restrict__ t_rr,
             float* __restrict__ f_r,
             float* __restrict__ t_br) {
    extern __shared__ char smem[];
    const uint32_t AH = smem_u32(smem);
    const uint32_t AL = AH + A_BYTES;
    const uint32_t BB = AL + A_BYTES;        // 34816-byte single B plane area

    const int tid  = threadIdx.x;
    const int wid  = tid >> 5;
    const int lane = tid & 31;
    const int wr   = wid & 3;
    const int wcg  = wid >> 2;

    const int a_row = wr * 16 + ((lane >> 3) & 1) * 8 + (lane & 7);
    const int a_kof = (lane >> 4) * 8;
    const int b_nof = ((lane >> 4) & 1) * 8 + (lane & 7);
    const int b_kof = ((lane >> 3) & 1) * 8;

    float acc[8][4];
#pragma unroll
    for (int o = 0; o < 8; o++)
#pragma unroll
        for (int j = 0; j < 4; j++) acc[o][j] = 0.0f;

    const bool robot = (blockIdx.x < GB_ROBOT);

    if (robot) {
        const int row0 = blockIdx.x * 64;
        const int M    = N_ROBOT;

        // ---- term 0: mean_rr(x_robot) @ Wl0_rr ----
        load_B34k_async(WB0_rr, BB, tid);            // hi plane
        cp_commit();
        load_A_gather(x_robot, off, cnt, csr, row0, M, AH, AL, wid, lane);
        cp_wait_all();
        __syncthreads();
        mainloop128_p<0>(AH, AL, BB, acc, a_row, a_kof, b_nof, b_kof, wcg);
        __syncthreads();
        load_B34k_async(WB0_rr + 8704, BB, tid);     // lo plane
        cp_commit(); cp_wait_all();
        __syncthreads();
        mainloop128_p<1>(AH, AL, BB, acc, a_row, a_kof, b_nof, b_kof, wcg);
        __syncthreads();

        // ---- term 1: mean_br(x_ball) @ Wl0_br ----
        load_B34k_async(WB0_br, BB, tid);
        cp_commit();
        load_A_gather(x_ball, off + N_ROBOT, cnt + N_ROBOT, csr, row0, M, AH, AL, wid, lane);
        cp_wait_all();
        __syncthreads();
        mainloop128_p<0>(AH, AL, BB, acc, a_row, a_kof, b_nof, b_kof, wcg);
        __syncthreads();
        load_B34k_async(WB0_br + 8704, BB, tid);
        cp_commit(); cp_wait_all();
        __syncthreads();
        mainloop128_p<1>(AH, AL, BB, acc, a_row, a_kof, b_nof, b_kof, wcg);
        __syncthreads();

        // ---- term 2: x_robot @ Wsum0 ----
        load_B34k_async(WBsum0, BB, tid);
        cp_commit();
        load_A_direct(x_robot, row0, M, AH, AL, tid);
        cp_wait_all();
        __syncthreads();
        mainloop128_p<0>(AH, AL, BB, acc, a_row, a_kof, b_nof, b_kof, wcg);
        __syncthreads();
        load_B34k_async(WBsum0 + 8704, BB, tid);
        cp_commit(); cp_wait_all();
        __syncthreads();
        mainloop128_p<1>(AH, AL, BB, acc, a_row, a_kof, b_nof, b_kof, wcg);
        __syncthreads();

        // ---- stage-2 tile 1 copy overlaps epilogue-1 ----
        load_B34k_async(WB1_rr, BB, tid);            // full hi+lo (N=64)
        cp_commit();
        {
            const int rAl = wr * 16 + (lane >> 2);
            const int rBl = rAl + 8;
#pragma unroll
            for (int o = 0; o < 8; o++) {
                int col = wcg * 64 + o * 8 + (lane & 3) * 2;
                float2 bv = *(const float2*)(bsum0 + col);
                float v0 = fmaxf(acc[o][0] + bv.x, 0.f);
                float v1 = fmaxf(acc[o][1] + bv.y, 0.f);
                float v2 = fmaxf(acc[o][2] + bv.x, 0.f);
                float v3 = fmaxf(acc[o][3] + bv.y, 0.f);
                uint32_t h, l;
                uint32_t offA = (uint32_t)rAl * STRIDE_B + (uint32_t)col * 2;
                split_pack(v0, v1, h, l);
                asm volatile("st.shared.b32 [%0], %1;" :: "r"(AH + offA), "r"(h) : "memory");
                asm volatile("st.shared.b32 [%0], %1;" :: "r"(AL + offA), "r"(l) : "memory");
                uint32_t offB = (uint32_t)rBl * STRIDE_B + (uint32_t)col * 2;
                split_pack(v2, v3, h, l);
                asm volatile("st.shared.b32 [%0], %1;" :: "r"(AH + offB), "r"(h) : "memory");
                asm volatile("st.shared.b32 [%0], %1;" :: "r"(AL + offB), "r"(l) : "memory");
            }
        }
        cp_wait_all();
        __syncthreads();

        float acc2a[4][4];
#pragma unroll
        for (int o = 0; o < 4; o++)
#pragma unroll
            for (int j = 0; j < 4; j++) acc2a[o][j] = 0.f;
        mainloop64(AH, AL, BB, BB + 17408, acc2a, a_row, a_kof, b_nof, b_kof, wcg);
        __syncthreads();

        load_B34k_async(WBsum1, BB, tid);
        cp_commit(); cp_wait_all();
        __syncthreads();

        float acc2b[4][4];
#pragma unroll
        for (int o = 0; o < 4; o++)
#pragma unroll
            for (int j = 0; j < 4; j++) acc2b[o][j] = 0.f;
        mainloop64(AH, AL, BB, BB + 17408, acc2b, a_row, a_kof, b_nof, b_kof, wcg);

        const int rA = row0 + wr * 16 + (lane >> 2);
        const int rB = rA + 8;
#pragma unroll
        for (int o = 0; o < 4; o++) {
            int col = wcg * 32 + o * 8 + (lane & 3) * 2;
            if (rA < M) {
                *(float2*)(t_rr + (size_t)rA * 64 + col) = make_float2(acc2a[o][0], acc2a[o][1]);
                *(float2*)(f_r  + (size_t)rA * 64 + col) = make_float2(acc2b[o][0], acc2b[o][1]);
            }
            if (rB < M) {
                *(float2*)(t_rr + (size_t)rB * 64 + col) = make_float2(acc2a[o][2], acc2a[o][3]);
                *(float2*)(f_r  + (size_t)rB * 64 + col) = make_float2(acc2b[o][2], acc2b[o][3]);
            }
        }
    } else {
        const int row0 = (blockIdx.x - GB_ROBOT) * 64;
        const int M    = N_BALL;

        // ---- term 0: mean_rb(x_robot) @ Wl0_rb ----
        load_B34k_async(WB0_rb, BB, tid);
        cp_commit();
        load_A_gather(x_robot, off + 2 * N_ROBOT, cnt + 2 * N_ROBOT, csr,
                      row0, M, AH, AL, wid, lane);
        cp_wait_all();
        __syncthreads();
        mainloop128_p<0>(AH, AL, BB, acc, a_row, a_kof, b_nof, b_kof, wcg);
        __syncthreads();
        load_B34k_async(WB0_rb + 8704, BB, tid);
        cp_commit(); cp_wait_all();
        __syncthreads();
        mainloop128_p<1>(AH, AL, BB, acc, a_row, a_kof, b_nof, b_kof, wcg);
        __syncthreads();

        // ---- term 1: x_ball @ Wr0_rb ----
        load_B34k_async(WBr0_rb, BB, tid);
        cp_commit();
        load_A_direct(x_ball, row0, M, AH, AL, tid);
        cp_wait_all();
        __syncthreads();
        mainloop128_p<0>(AH, AL, BB, acc, a_row, a_kof, b_nof, b_kof, wcg);
        __syncthreads();
        load_B34k_async(WBr0_rb + 8704, BB, tid);
        cp_commit(); cp_wait_all();
        __syncthreads();
        mainloop128_p<1>(AH, AL, BB, acc, a_row, a_kof, b_nof, b_kof, wcg);
        __syncthreads();

        load_B34k_async(WB1_br, BB, tid);
        cp_commit();
        {
            const int rAl = wr * 16 + (lane >> 2);
            const int rBl = rAl + 8;
#pragma unroll
            for (int o = 0; o < 8; o++) {
                int col = wcg * 64 + o * 8 + (lane & 3) * 2;
                float2 bv = *(const float2*)(b0_rb + col);
                float v0 = fmaxf(acc[o][0] + bv.x, 0.f);
                float v1 = fmaxf(acc[o][1] + bv.y, 0.f);
                float v2 = fmaxf(acc[o][2] + bv.x, 0.f);
                float v3 = fmaxf(acc[o][3] + bv.y, 0.f);
                uint32_t h, l;
                uint32_t offA = (uint32_t)rAl * STRIDE_B + (uint32_t)col * 2;
                split_pack(v0, v1, h, l);
                asm volatile("st.shared.b32 [%0], %1;" :: "r"(AH + offA), "r"(h) : "memory");
                asm volatile("st.shared.b32 [%0], %1;" :: "r"(AL + offA), "r"(l) : "memory");
                uint32_t offB = (uint32_t)rBl * STRIDE_B + (uint32_t)col * 2;
                split_pack(v2, v3, h, l);
                asm volatile("st.shared.b32 [%0], %1;" :: "r"(AH + offB), "r"(h) : "memory");
                asm volatile("st.shared.b32 [%0], %1;" :: "r"(AL + offB), "r"(l) : "memory");
            }
        }
        cp_wait_all();
        __syncthreads();

        float acc2[4][4];
#pragma unroll
        for (int o = 0; o < 4; o++)
#pragma unroll
            for (int j = 0; j < 4; j++) acc2[o][j] = 0.f;
        mainloop64(AH, AL, BB, BB + 17408, acc2, a_row, a_kof, b_nof, b_kof, wcg);

        const int rA = row0 + wr * 16 + (lane >> 2);
        const int rB = rA + 8;
#pragma unroll
        for (int o = 0; o < 4; o++) {
            int col = wcg * 32 + o * 8 + (lane & 3) * 2;
            if (rA < M)
                *(float2*)(t_br + (size_t)rA * 64 + col) = make_float2(acc2[o][0], acc2[o][1]);
            if (rB < M)
                *(float2*)(t_br + (size_t)rB * 64 + col) = make_float2(acc2[o][2], acc2[o][3]);
        }
    }
}

// ---------------------------------------------------------------------------
// Final: out[d] = mean_rr(t_rr) + mean_br(t_br) + f_r[d] + bsum1
// ---------------------------------------------------------------------------
__device__ __forceinline__ float2 row_load64(const float* __restrict__ t,
                                             int s, int lane) {
    return *(const float2*)(t + (size_t)s * 64 + lane * 2);
}

__device__ __forceinline__ void tail64(const float* __restrict__ t,
                                       const int* __restrict__ csr,
                                       int st, int& j, int dg,
                                       int lane, float2& a) {
    for (; j + 4 <= dg; j += 4) {
        int s0 = csr[st + j], s1 = csr[st + j + 1];
        int s2 = csr[st + j + 2], s3 = csr[st + j + 3];
        float2 v0 = row_load64(t, s0, lane);
        float2 v1 = row_load64(t, s1, lane);
        float2 v2 = row_load64(t, s2, lane);
        float2 v3 = row_load64(t, s3, lane);
        a.x += (v0.x + v1.x) + (v2.x + v3.x);
        a.y += (v0.y + v1.y) + (v2.y + v3.y);
    }
    if (j + 2 <= dg) {
        int s0 = csr[st + j], s1 = csr[st + j + 1];
        float2 v0 = row_load64(t, s0, lane);
        float2 v1 = row_load64(t, s1, lane);
        a.x += v0.x + v1.x; a.y += v0.y + v1.y;
        j += 2;
    }
    if (j < dg) {
        float2 v = row_load64(t, csr[st + j], lane);
        a.x += v.x; a.y += v.y;
    }
}

__global__ void __launch_bounds__(256)
final_kernel(const int* __restrict__ off_rr, const int* __restrict__ cnt_rr,
             const int* __restrict__ off_br, const int* __restrict__ cnt_br,
             const int* __restrict__ csr,
             const float* __restrict__ t_rr, const float* __restrict__ t_br,
             const float* __restrict__ f_r, const float* __restrict__ bsum1,
             float* __restrict__ out) {
    int warp = (blockIdx.x * blockDim.x + threadIdx.x) >> 5;
    int lane = threadIdx.x & 31;
    if (warp >= N_ROBOT) return;

    float2 res = *(const float2*)(f_r + (size_t)warp * 64 + lane * 2);
    float2 bv  = *(const float2*)(bsum1 + lane * 2);
    res.x += bv.x; res.y += bv.y;

    int st0 = off_rr[warp], dg0 = cnt_rr[warp];
    int st1 = off_br[warp], dg1 = cnt_br[warp];
    float2 a0 = make_float2(0.f, 0.f);
    float2 a1 = make_float2(0.f, 0.f);
    int j0 = 0, j1 = 0;
    tail64(t_rr, csr, st0, j0, dg0, lane, a0);
    tail64(t_br, csr, st1, j1, dg1, lane, a1);

    float inv0 = (dg0 > 0) ? (1.0f / (float)dg0) : 0.0f;
    float inv1 = (dg1 > 0) ? (1.0f / (float)dg1) : 0.0f;
    res.x += a0.x * inv0 + a1.x * inv1;
    res.y += a0.y * inv0 + a1.y * inv1;

    *(float2*)(out + (size_t)warp * 64 + lane * 2) = res;
}

// ---------------------------------------------------------------------------
// Launch: memset(0) count3(1) scanprep(2) fill3(3) fused(4) final(5)
// ---------------------------------------------------------------------------
extern "C" void kernel_launch(void* const* d_in, const int* in_sizes, int n_in,
                              void* d_out, int out_size) {
    (void)n_in; (void)out_size;

    const float* x_robot = (const float*)d_in[0];
    const float* x_ball  = (const float*)d_in[1];
    const int* ei_rr = (const int*)d_in[2];
    const int* ei_rb = (const int*)d_in[3];
    const int* ei_br = (const int*)d_in[4];
    const float* Wl0_rr = (const float*)d_in[5];
    const float* Wr0_rr = (const float*)d_in[6];
    const float* b0_rr  = (const float*)d_in[7];
    const float* Wl0_rb = (const float*)d_in[8];
    const float* Wr0_rb = (const float*)d_in[9];
    const float* b0_rb  = (const float*)d_in[10];
    const float* Wl0_br = (const float*)d_in[11];
    const float* Wr0_br = (const float*)d_in[12];
    const float* b0_br  = (const float*)d_in[13];
    const float* Wl1_rr = (const float*)d_in[14];
    const float* Wr1_rr = (const float*)d_in[15];
    const float* b1_rr  = (const float*)d_in[16];
    const float* Wl1_br = (const float*)d_in[20];
    const float* Wr1_br = (const float*)d_in[21];
    const float* b1_br  = (const float*)d_in[22];

    float* out = (float*)d_out;
    const int E = in_sizes[2] / 2;

    float* S = nullptr;
    int *C = nullptr, *OFF = nullptr, *CUR = nullptr, *CSR = nullptr;
    {
        void* p = nullptr;
        cudaGetSymbolAddress(&p, g_scratch); S = (float*)p;
        cudaGetSymbolAddress(&p, g_cnt);     C = (int*)p;
        cudaGetSymbolAddress(&p, g_off);     OFF = (int*)p;
        cudaGetSymbolAddress(&p, g_cursor);  CUR = (int*)p;
        cudaGetSymbolAddress(&p, g_csr);     CSR = (int*)p;
    }
    unsigned long long* STATE = (unsigned long long*)(C + 3 * N_ROBOT);

    float* t_rr    = S + O_TRR;
    float* t_br    = S + O_TBR;
    float* f_r     = S + O_FR;
    float* bsum0   = S + O_BSUM0;
    float* bsum1   = S + O_BSUM1;
    float* WB0_rr  = S + O_WB0_RR;
    float* WB0_br  = S + O_WB0_BR;
    float* WBsum0  = S + O_WBSUM0;
    float* WB0_rb  = S + O_WB0_RB;
    float* WBr0_rb = S + O_WBR0_RB;
    float* WB1_rr  = S + O_WB1_RR;
    float* WBsum1  = S + O_WBSUM1;
    float* WB1_br  = S + O_WB1_BR;

    cudaFuncSetAttribute(fused_kernel,
                         cudaFuncAttributeMaxDynamicSharedMemorySize, SMEM_TOTAL);

    // idx 0: zero counts + lookback state
    cudaMemsetAsync(C, 0, (3ull * N_ROBOT + 2048ull) * sizeof(int), 0);

    // idx 1: counts
    const int cb3 = (3 * E + 255) / 256;
    count3_kernel<<<cb3, 256>>>(ei_rr + E, ei_br + E, ei_rb + E, C, E);

    // idx 2: single-pass scan + weight/bias prep
    scanprep_kernel<<<SCAN_NB + PREP_NB, 512>>>(
        C, OFF, CUR, STATE,
        Wl0_rr, Wl0_br, Wr0_rr, Wr0_br, Wl0_rb, Wr0_rb,
        Wl1_rr, Wr1_rr, Wr1_br, Wl1_br,
        b0_rr, b0_br, b1_rr, b1_br,
        WB0_rr, WB0_br, WBsum0, WB0_rb, WBr0_rb,
        WB1_rr, WBsum1, WB1_br, bsum0, bsum1);

    // idx 3: CSR fill
    fill3_csr_kernel<<<cb3, 256>>>(ei_rr, ei_rr + E, ei_br, ei_br + E,
                                   ei_rb, ei_rb + E, CUR, CSR, E);

    // idx 4: fused compute (3 CTAs/SM)
    fused_kernel<<<GB_ROBOT + GB_BALL, 256, SMEM_TOTAL>>>(
        x_robot, x_ball, OFF, C, CSR,
        WB0_rr, WB0_br, WBsum0, bsum0, WB1_rr, WBsum1,
        WB0_rb, WBr0_rb, b0_rb, WB1_br,
        t_rr, f_r, t_br);

    // idx 5: final combine
    const int fb = (N_ROBOT * 32 + 255) / 256;
    final_kernel<<<fb, 256>>>(OFF, C, OFF + N_ROBOT, C + N_ROBOT, CSR,
                              t_rr, t_br, f_r, bsum1, out);
}